// round 7
// baseline (speedup 1.0000x reference)
#include <cuda_runtime.h>
#include <cuda_bf16.h>
#include <cstdint>
#include <cstddef>

// Problem constants
#define B_ 8
#define S_ 4096
#define D_ 512
#define C_ 16                 // chunk length
#define NCH_ (S_ / C_)        // 256 chunks
#define M_TOT (B_ * S_)       // 32768

static __device__ __constant__ float kEPS = 1e-6f;

// ---------------------------------------------------------------------------
// Scratch (device globals: no allocation allowed)
// ---------------------------------------------------------------------------
__device__ float g_q[(size_t)B_ * S_ * D_];
__device__ float g_k[(size_t)B_ * S_ * D_];
__device__ float g_v[(size_t)B_ * S_ * D_];
__device__ float g_a[(size_t)B_ * S_ * D_];

// bf16 hi/lo split operands for tensor-core projections
__device__ __nv_bfloat16 g_xhi[(size_t)M_TOT * D_];
__device__ __nv_bfloat16 g_xlo[(size_t)M_TOT * D_];
__device__ __nv_bfloat16 g_whi[4 * D_ * D_];
__device__ __nv_bfloat16 g_wlo[4 * D_ * D_];

// ---------------------------------------------------------------------------
// f32x2 packed-math helpers (scan)
// ---------------------------------------------------------------------------
typedef unsigned long long u64;

__device__ __forceinline__ u64 pack2(float lo, float hi) {
    u64 r;
    asm("mov.b64 %0, {%1, %2};" : "=l"(r) : "f"(lo), "f"(hi));
    return r;
}
__device__ __forceinline__ void unpack2(u64 v, float& lo, float& hi) {
    asm("mov.b64 {%0, %1}, %2;" : "=f"(lo), "=f"(hi) : "l"(v));
}
__device__ __forceinline__ u64 fma2(u64 a, u64 b, u64 c) {
    u64 d;
    asm("fma.rn.f32x2 %0, %1, %2, %3;" : "=l"(d) : "l"(a), "l"(b), "l"(c));
    return d;
}
__device__ __forceinline__ u64 mul2(u64 a, u64 b) {
    u64 d;
    asm("mul.rn.f32x2 %0, %1, %2;" : "=l"(d) : "l"(a), "l"(b));
    return d;
}

// ---------------------------------------------------------------------------
// Tensor-core helpers
// ---------------------------------------------------------------------------
__device__ __forceinline__ uint32_t smem_u32(const void* p) {
    uint32_t a;
    asm("{ .reg .u64 t; cvta.to.shared.u64 t, %1; cvt.u32.u64 %0, t; }"
        : "=r"(a) : "l"(p));
    return a;
}
__device__ __forceinline__ void ldsm4(uint32_t* r, uint32_t addr) {
    asm volatile("ldmatrix.sync.aligned.m8n8.x4.shared.b16 {%0,%1,%2,%3}, [%4];"
                 : "=r"(r[0]), "=r"(r[1]), "=r"(r[2]), "=r"(r[3]) : "r"(addr));
}
__device__ __forceinline__ void mma16816(float* c, const uint32_t* a,
                                         uint32_t b0, uint32_t b1) {
    asm volatile(
        "mma.sync.aligned.m16n8k16.row.col.f32.bf16.bf16.f32 "
        "{%0,%1,%2,%3}, {%4,%5,%6,%7}, {%8,%9}, {%0,%1,%2,%3};"
        : "+f"(c[0]), "+f"(c[1]), "+f"(c[2]), "+f"(c[3])
        : "r"(a[0]), "r"(a[1]), "r"(a[2]), "r"(a[3]), "r"(b0), "r"(b1));
}
__device__ __forceinline__ void cp16(uint32_t saddr, const void* g) {
    asm volatile("cp.async.cg.shared.global [%0], [%1], 16;"
                 :: "r"(saddr), "l"(g));
}

__device__ __forceinline__ float act_apply(float x, int act) {
    if (act == 1) return fmaxf(x, 0.0f);               // relu
    if (act == 2) return 1.0f / (1.0f + __expf(-x));   // sigmoid
    return x;
}

// ---------------------------------------------------------------------------
// fp32 -> bf16 hi/lo split (x = hi + lo to ~2^-16 rel)
// ---------------------------------------------------------------------------
__global__ void __launch_bounds__(256) convert_split_kernel(
    const float* __restrict__ src,
    __nv_bfloat16* __restrict__ hi,
    __nv_bfloat16* __restrict__ lo, int n2)
{
    const int idx = blockIdx.x * blockDim.x + threadIdx.x;
    const int stride = gridDim.x * blockDim.x;
    const float2* s2 = (const float2*)src;
    __nv_bfloat162* h2 = (__nv_bfloat162*)hi;
    __nv_bfloat162* l2 = (__nv_bfloat162*)lo;
    for (int i = idx; i < n2; i += stride) {
        const float2 x = s2[i];
        const __nv_bfloat16 h0 = __float2bfloat16(x.x);
        const __nv_bfloat16 h1 = __float2bfloat16(x.y);
        __nv_bfloat162 hh; hh.x = h0; hh.y = h1;
        __nv_bfloat162 ll;
        ll.x = __float2bfloat16(x.x - __bfloat162float(h0));
        ll.y = __float2bfloat16(x.y - __bfloat162float(h1));
        h2[i] = hh;
        l2[i] = ll;
    }
}

// All 4 weights in one launch (blockIdx.y = weight index)
__global__ void __launch_bounds__(256) convert_w_kernel(
    const float* __restrict__ w0, const float* __restrict__ w1,
    const float* __restrict__ w2, const float* __restrict__ w3)
{
    const int wsel = blockIdx.y;
    const float* src = (wsel == 0) ? w0 : (wsel == 1) ? w1 : (wsel == 2) ? w2 : w3;
    __nv_bfloat162* h2 = (__nv_bfloat162*)(g_whi + (size_t)wsel * D_ * D_);
    __nv_bfloat162* l2 = (__nv_bfloat162*)(g_wlo + (size_t)wsel * D_ * D_);
    const float2* s2 = (const float2*)src;
    const int n2 = (D_ * D_) / 2;
    const int idx = blockIdx.x * blockDim.x + threadIdx.x;
    const int stride = gridDim.x * blockDim.x;
    for (int i = idx; i < n2; i += stride) {
        const float2 x = s2[i];
        const __nv_bfloat16 h0 = __float2bfloat16(x.x);
        const __nv_bfloat16 h1 = __float2bfloat16(x.y);
        __nv_bfloat162 hh; hh.x = h0; hh.y = h1;
        __nv_bfloat162 ll;
        ll.x = __float2bfloat16(x.x - __bfloat162float(h0));
        ll.y = __float2bfloat16(x.y - __bfloat162float(h1));
        h2[i] = hh;
        l2[i] = ll;
    }
}

// ---------------------------------------------------------------------------
// Tensor-core projection GEMM (unchanged from round 6)
// ---------------------------------------------------------------------------
#define GK 32
#define NKCH (D_ / GK)
#define ROWB 80
#define TILEB (128 * ROWB)
#define ABUF_HI 0
#define ABUF_LO TILEB
#define BBUF_HI (2 * TILEB)
#define BBUF_LO (3 * TILEB)
#define BUFB (4 * TILEB)
#define GEMM_SMEM (2 * BUFB)

__global__ void __launch_bounds__(256, 1) proj_mma_kernel(
    const float* __restrict__ bq, const float* __restrict__ bk,
    const float* __restrict__ bv, const float* __restrict__ ba)
{
    extern __shared__ __align__(16) char smem[];
    const uint32_t sbase = smem_u32(smem);

    const int pz = blockIdx.z;
    const float* bias;
    float* out;
    int act;
    if (pz == 0)      { bias = bq; out = g_q; act = 1; }
    else if (pz == 1) { bias = bk; out = g_k; act = 1; }
    else if (pz == 2) { bias = bv; out = g_v; act = 0; }
    else              { bias = ba; out = g_a; act = 2; }

    const int tid = threadIdx.x;
    const int w = tid >> 5;
    const int l = tid & 31;
    const int wm = w >> 2;
    const int wn = w & 3;

    const int mBase = blockIdx.y * 128;
    const int nBase = blockIdx.x * 128;

    const __nv_bfloat16* Whi = g_whi + (size_t)pz * D_ * D_;
    const __nv_bfloat16* Wlo = g_wlo + (size_t)pz * D_ * D_;

    const int slot0 = tid;
    const int slot1 = tid + 256;
    const int r0s = slot0 >> 2, s0s = slot0 & 3;
    const int r1s = slot1 >> 2, s1s = slot1 & 3;

    auto load_chunk = [&](int buf, int kc) {
        const uint32_t sb = sbase + buf * BUFB;
        const int k0 = kc * GK;
        {
            const size_t ga = (size_t)(mBase + r0s) * D_ + k0 + s0s * 8;
            const size_t gb = (size_t)(nBase + r0s) * D_ + k0 + s0s * 8;
            const uint32_t so = r0s * ROWB + s0s * 16;
            cp16(sb + ABUF_HI + so, g_xhi + ga);
            cp16(sb + ABUF_LO + so, g_xlo + ga);
            cp16(sb + BBUF_HI + so, Whi + gb);
            cp16(sb + BBUF_LO + so, Wlo + gb);
        }
        {
            const size_t ga = (size_t)(mBase + r1s) * D_ + k0 + s1s * 8;
            const size_t gb = (size_t)(nBase + r1s) * D_ + k0 + s1s * 8;
            const uint32_t so = r1s * ROWB + s1s * 16;
            cp16(sb + ABUF_HI + so, g_xhi + ga);
            cp16(sb + ABUF_LO + so, g_xlo + ga);
            cp16(sb + BBUF_HI + so, Whi + gb);
            cp16(sb + BBUF_LO + so, Wlo + gb);
        }
        asm volatile("cp.async.commit_group;");
    };

    float acc[4][4][4];
#pragma unroll
    for (int i = 0; i < 4; ++i)
#pragma unroll
        for (int j = 0; j < 4; ++j)
#pragma unroll
            for (int e = 0; e < 4; ++e) acc[i][j][e] = 0.0f;

    const int lrow = l & 15;
    const int lcol16 = (l >> 4) & 1;

    load_chunk(0, 0);

#pragma unroll 1
    for (int kc = 0; kc < NKCH; ++kc) {
        const int buf = kc & 1;
        if (kc + 1 < NKCH) {
            load_chunk(buf ^ 1, kc + 1);
            asm volatile("cp.async.wait_group 1;");
        } else {
            asm volatile("cp.async.wait_group 0;");
        }
        __syncthreads();

        const uint32_t sb = sbase + buf * BUFB;
#pragma unroll
        for (int kh = 0; kh < 2; ++kh) {
            const uint32_t coff = kh * 32 + lcol16 * 16;
            uint32_t ah[4][4], al[4][4];
#pragma unroll
            for (int mt = 0; mt < 4; ++mt) {
                const uint32_t ra = (wm * 64 + mt * 16 + lrow) * ROWB + coff;
                ldsm4(ah[mt], sb + ABUF_HI + ra);
                ldsm4(al[mt], sb + ABUF_LO + ra);
            }
            uint32_t bh[2][4], bl[2][4];
#pragma unroll
            for (int bt = 0; bt < 2; ++bt) {
                const uint32_t rb = (wn * 32 + bt * 16 + lrow) * ROWB + coff;
                ldsm4(bh[bt], sb + BBUF_HI + rb);
                ldsm4(bl[bt], sb + BBUF_LO + rb);
            }
#pragma unroll
            for (int mt = 0; mt < 4; ++mt)
#pragma unroll
                for (int nt = 0; nt < 4; ++nt) {
                    const int bt = nt >> 1;
                    const int hf = nt & 1;
                    mma16816(acc[mt][nt], ah[mt], bh[bt][hf], bh[bt][hf + 2]);
                    mma16816(acc[mt][nt], ah[mt], bl[bt][hf], bl[bt][hf + 2]);
                    mma16816(acc[mt][nt], al[mt], bh[bt][hf], bh[bt][hf + 2]);
                }
        }
        __syncthreads();
    }

#pragma unroll
    for (int nt = 0; nt < 4; ++nt) {
        const int col = nBase + wn * 32 + nt * 8 + 2 * (l & 3);
        const float2 b2 = *(const float2*)(bias + col);
#pragma unroll
        for (int mt = 0; mt < 4; ++mt) {
            const int row = mBase + wm * 64 + mt * 16 + (l >> 2);
            float2 r0, r1;
            r0.x = act_apply(acc[mt][nt][0] + b2.x, act);
            r0.y = act_apply(acc[mt][nt][1] + b2.y, act);
            r1.x = act_apply(acc[mt][nt][2] + b2.x, act);
            r1.y = act_apply(acc[mt][nt][3] + b2.y, act);
            *(float2*)(out + (size_t)row * D_ + col) = r0;
            *(float2*)(out + (size_t)(row + 8) * D_ + col) = r1;
        }
    }
}

// ---------------------------------------------------------------------------
// Chunked scan — round-5 structure, but the pp loop is now FULLY unrolled so
// the state array su[16] stays in registers (partial unroll forced it to
// local memory: dynamically-indexed register arrays are demoted by ptxas).
// ---------------------------------------------------------------------------
#define SM_QTP  0
#define SM_KTP  (SM_QTP + 256*36)
#define SM_ACP  (SM_KTP + 256*36)
#define SM_V    (SM_ACP + 512)
#define SM_PART (SM_V + 512)
#define SM_DEN  (SM_PART + 16*32*17)
#define SM_FLOATS (SM_DEN + 512*17)
#define SCAN_SMEM_BYTES (SM_FLOATS * 4)

__global__ void __launch_bounds__(512, 1) scan_chunk_kernel(float* __restrict__ y)
{
    extern __shared__ __align__(16) float sm[];
    float* sQtp = sm + SM_QTP;
    float* sKtp = sm + SM_KTP;
    float* sACp = sm + SM_ACP;
    float* sV   = sm + SM_V;
    float* sPart= sm + SM_PART;
    float* sDen = sm + SM_DEN;

    const int b = blockIdx.y;
    const int jbase = blockIdx.x * 32;
    const int tid = threadIdx.x;
    const int w = tid >> 5;
    const int c = tid & 31;

    const float* gq = g_q + (size_t)b * S_ * D_;
    const float* gk = g_k + (size_t)b * S_ * D_;
    const float* gv = g_v + (size_t)b * S_ * D_;
    const float* ga = g_a + (size_t)b * S_ * D_;
    float* gy = y + (size_t)b * S_ * D_;

    u64 su[16];
#pragma unroll
    for (int pp = 0; pp < 16; ++pp) su[pp] = 0ull;
    float zreg = 0.0f;

    const int i_ = tid;
    const int p_ = i_ >> 1;
    const int hv_ = i_ & 1;

    {
        const int tpf = c & 15;
        const size_t roff = (size_t)tpf * D_ + w * 32;
        if (c < 16) {
            asm volatile("prefetch.global.L2 [%0];" :: "l"(gq + roff));
            asm volatile("prefetch.global.L2 [%0];" :: "l"(ga + roff));
        } else {
            asm volatile("prefetch.global.L2 [%0];" :: "l"(gk + roff));
            if (w == 0)
                asm volatile("prefetch.global.L2 [%0];"
                             :: "l"(gv + (size_t)tpf * D_ + jbase));
        }
    }

#pragma unroll 1
    for (int ch = 0; ch < NCH_; ++ch) {
        const int t0 = ch * C_;

        __syncthreads();   // B0

        {
            float av[16], qv[16], kv[16];
#pragma unroll
            for (int t = 0; t < 16; ++t) av[t] = ga[(size_t)(t0 + t) * D_ + i_];
#pragma unroll
            for (int t = 0; t < 16; ++t) qv[t] = gq[(size_t)(t0 + t) * D_ + i_];
#pragma unroll
            for (int t = 0; t < 16; ++t) kv[t] = gk[(size_t)(t0 + t) * D_ + i_];

            float A[16], invA[16];
            A[0] = av[0];
#pragma unroll
            for (int t = 1; t < 16; ++t) A[t] = A[t - 1] * av[t];
            invA[15] = __frcp_rn(A[15]);
#pragma unroll
            for (int t = 15; t >= 1; --t) invA[t - 1] = invA[t] * av[t];

            float zu = zreg;
#pragma unroll
            for (int t = 0; t < 16; ++t) {
                const float qt = qv[t] * A[t];
                const float kt = kv[t] * invA[t];
                zu += kt;
                sDen[i_ * 17 + t] = qt * zu;
                sQtp[p_ * 36 + t * 2 + hv_] = qt;
                sKtp[p_ * 36 + t * 2 + hv_] = kt;
            }
            zreg = A[15] * zu;
            sACp[p_ * 2 + hv_] = A[15];
        }

        if (tid < 128) {
            const int tv = tid >> 3;
            const int c4 = (tid & 7) << 2;
            const float4 vv = *(const float4*)(gv + (size_t)(t0 + tv) * D_ + jbase + c4);
            *(float4*)&sV[tv * 32 + c4] = vv;
        }

        __syncthreads();   // B1

        if (ch + 1 < NCH_) {
            const int tpf = c & 15;
            const size_t roff = (size_t)(t0 + 16 + tpf) * D_ + w * 32;
            if (c < 16) {
                asm volatile("prefetch.global.L2 [%0];" :: "l"(gq + roff));
                asm volatile("prefetch.global.L2 [%0];" :: "l"(ga + roff));
            } else {
                asm volatile("prefetch.global.L2 [%0];" :: "l"(gk + roff));
                if (w == 0)
                    asm volatile("prefetch.global.L2 [%0];"
                                 :: "l"(gv + (size_t)(t0 + 16 + tpf) * D_ + jbase));
            }
        }

        // ---------------- main loop (pp loop FULLY unrolled) ----------------
#pragma unroll
        for (int th = 0; th < 2; ++th) {
            u64 vd[8];
#pragma unroll
            for (int tt = 0; tt < 8; ++tt) {
                const float vv = sV[(th * 8 + tt) * 32 + c];
                vd[tt] = pack2(vv, vv);
            }
            u64 nacc[8];
#pragma unroll
            for (int tt = 0; tt < 8; ++tt) nacc[tt] = 0ull;

#pragma unroll
            for (int pp = 0; pp < 16; ++pp) {
                const int p = w * 16 + pp;
                const ulonglong2* kr = (const ulonglong2*)(sKtp + p * 36 + th * 16);
                const ulonglong2* qr = (const ulonglong2*)(sQtp + p * 36 + th * 16);
                const ulonglong2 k01 = kr[0], k23 = kr[1], k45 = kr[2], k67 = kr[3];
                const ulonglong2 q01 = qr[0], q23 = qr[1], q45 = qr[2], q67 = qr[3];
                u64 s = su[pp];
                s = fma2(k01.x, vd[0], s); nacc[0] = fma2(q01.x, s, nacc[0]);
                s = fma2(k01.y, vd[1], s); nacc[1] = fma2(q01.y, s, nacc[1]);
                s = fma2(k23.x, vd[2], s); nacc[2] = fma2(q23.x, s, nacc[2]);
                s = fma2(k23.y, vd[3], s); nacc[3] = fma2(q23.y, s, nacc[3]);
                s = fma2(k45.x, vd[4], s); nacc[4] = fma2(q45.x, s, nacc[4]);
                s = fma2(k45.y, vd[5], s); nacc[5] = fma2(q45.y, s, nacc[5]);
                s = fma2(k67.x, vd[6], s); nacc[6] = fma2(q67.x, s, nacc[6]);
                s = fma2(k67.y, vd[7], s); nacc[7] = fma2(q67.y, s, nacc[7]);
                su[pp] = s;
            }

#pragma unroll
            for (int tt = 0; tt < 8; ++tt) {
                float lo, hi;
                unpack2(nacc[tt], lo, hi);
                sPart[((th * 8 + tt) * 32 + c) * 17 + w] = lo + hi;
            }
        }

#pragma unroll
        for (int pp = 0; pp < 16; ++pp) {
            const u64 acp = *(const u64*)(sACp + (w * 16 + pp) * 2);
            su[pp] = mul2(su[pp], acp);
        }

        __syncthreads();   // B2

        {
            const int t = w;
            float num = 0.0f;
            float dpart = 0.0f;
#pragma unroll
            for (int ww = 0; ww < 16; ++ww) {
                num   += sPart[(t * 32 + c) * 17 + ww];
                dpart += sDen[(ww * 32 + c) * 17 + t];
            }
#pragma unroll
            for (int off = 16; off; off >>= 1)
                dpart += __shfl_xor_sync(0xffffffffu, dpart, off);
            const float inv = 1.0f / (dpart + kEPS);
            gy[(size_t)(t0 + t) * D_ + jbase + c] = num * inv;
        }
    }
}

// ---------------------------------------------------------------------------
// Launch
// ---------------------------------------------------------------------------
extern "C" void kernel_launch(void* const* d_in, const int* in_sizes, int n_in,
                              void* d_out, int out_size)
{
    const float* x  = (const float*)d_in[0];
    const float* Wq = (const float*)d_in[1];
    const float* bq = (const float*)d_in[2];
    const float* Wk = (const float*)d_in[3];
    const float* bk = (const float*)d_in[4];
    const float* Wv = (const float*)d_in[5];
    const float* bv = (const float*)d_in[6];
    const float* Wa = (const float*)d_in[7];
    const float* ba = (const float*)d_in[8];
    float* y = (float*)d_out;

    static __nv_bfloat16 *p_xhi = nullptr, *p_xlo = nullptr;
    if (!p_xhi) {
        cudaGetSymbolAddress((void**)&p_xhi, g_xhi);
        cudaGetSymbolAddress((void**)&p_xlo, g_xlo);
    }

    // 1) fp32 -> bf16 hi/lo splits
    convert_split_kernel<<<2048, 256>>>(x, p_xhi, p_xlo, (M_TOT * D_) / 2);
    dim3 wgrid(64, 4);
    convert_w_kernel<<<wgrid, 256>>>(Wq, Wk, Wv, Wa);

    // 2) tensor-core projections
    cudaFuncSetAttribute(proj_mma_kernel,
                         cudaFuncAttributeMaxDynamicSharedMemorySize, GEMM_SMEM);
    dim3 ggrid(D_ / 128, M_TOT / 128, 4);
    proj_mma_kernel<<<ggrid, 256, GEMM_SMEM>>>(bq, bk, bv, ba);

    // 3) chunked scan
    cudaFuncSetAttribute(scan_chunk_kernel,
                         cudaFuncAttributeMaxDynamicSharedMemorySize,
                         SCAN_SMEM_BYTES);
    dim3 sgrid(D_ / 32, B_);
    scan_chunk_kernel<<<sgrid, 512, SCAN_SMEM_BYTES>>>(y);
}

// round 8
// speedup vs baseline: 1.6190x; 1.6190x over previous
#include <cuda_runtime.h>
#include <cuda_bf16.h>
#include <cstdint>
#include <cstddef>

// Problem constants
#define B_ 8
#define S_ 4096
#define D_ 512
#define C_ 16                 // chunk length
#define NCH_ (S_ / C_)        // 256 chunks
#define M_TOT (B_ * S_)       // 32768

static __device__ __constant__ float kEPS = 1e-6f;

// ---------------------------------------------------------------------------
// Scratch (device globals: no allocation allowed)
// ---------------------------------------------------------------------------
__device__ float g_q[(size_t)B_ * S_ * D_];
__device__ float g_k[(size_t)B_ * S_ * D_];
__device__ float g_v[(size_t)B_ * S_ * D_];
__device__ float g_a[(size_t)B_ * S_ * D_];

// bf16 hi/lo split operands for tensor-core projections
__device__ __nv_bfloat16 g_xhi[(size_t)M_TOT * D_];
__device__ __nv_bfloat16 g_xlo[(size_t)M_TOT * D_];
__device__ __nv_bfloat16 g_whi[4 * D_ * D_];
__device__ __nv_bfloat16 g_wlo[4 * D_ * D_];

// ---------------------------------------------------------------------------
// f32x2 packed-math helpers (scan)
// ---------------------------------------------------------------------------
typedef unsigned long long u64;

__device__ __forceinline__ u64 pack2(float lo, float hi) {
    u64 r;
    asm("mov.b64 %0, {%1, %2};" : "=l"(r) : "f"(lo), "f"(hi));
    return r;
}
__device__ __forceinline__ void unpack2(u64 v, float& lo, float& hi) {
    asm("mov.b64 {%0, %1}, %2;" : "=f"(lo), "=f"(hi) : "l"(v));
}
__device__ __forceinline__ u64 fma2(u64 a, u64 b, u64 c) {
    u64 d;
    asm("fma.rn.f32x2 %0, %1, %2, %3;" : "=l"(d) : "l"(a), "l"(b), "l"(c));
    return d;
}
__device__ __forceinline__ u64 mul2(u64 a, u64 b) {
    u64 d;
    asm("mul.rn.f32x2 %0, %1, %2;" : "=l"(d) : "l"(a), "l"(b));
    return d;
}

// ---------------------------------------------------------------------------
// Tensor-core helpers
// ---------------------------------------------------------------------------
__device__ __forceinline__ uint32_t smem_u32(const void* p) {
    uint32_t a;
    asm("{ .reg .u64 t; cvta.to.shared.u64 t, %1; cvt.u32.u64 %0, t; }"
        : "=r"(a) : "l"(p));
    return a;
}
__device__ __forceinline__ void ldsm4(uint32_t* r, uint32_t addr) {
    asm volatile("ldmatrix.sync.aligned.m8n8.x4.shared.b16 {%0,%1,%2,%3}, [%4];"
                 : "=r"(r[0]), "=r"(r[1]), "=r"(r[2]), "=r"(r[3]) : "r"(addr));
}
__device__ __forceinline__ void mma16816(float* c, const uint32_t* a,
                                         uint32_t b0, uint32_t b1) {
    asm volatile(
        "mma.sync.aligned.m16n8k16.row.col.f32.bf16.bf16.f32 "
        "{%0,%1,%2,%3}, {%4,%5,%6,%7}, {%8,%9}, {%0,%1,%2,%3};"
        : "+f"(c[0]), "+f"(c[1]), "+f"(c[2]), "+f"(c[3])
        : "r"(a[0]), "r"(a[1]), "r"(a[2]), "r"(a[3]), "r"(b0), "r"(b1));
}
__device__ __forceinline__ void cp16(uint32_t saddr, const void* g) {
    asm volatile("cp.async.cg.shared.global [%0], [%1], 16;"
                 :: "r"(saddr), "l"(g));
}

__device__ __forceinline__ float act_apply(float x, int act) {
    if (act == 1) return fmaxf(x, 0.0f);               // relu
    if (act == 2) return 1.0f / (1.0f + __expf(-x));   // sigmoid
    return x;
}

// ---------------------------------------------------------------------------
// fp32 -> bf16 hi/lo split (x = hi + lo to ~2^-16 rel)
// ---------------------------------------------------------------------------
__global__ void __launch_bounds__(256) convert_split_kernel(
    const float* __restrict__ src,
    __nv_bfloat16* __restrict__ hi,
    __nv_bfloat16* __restrict__ lo, int n2)
{
    const int idx = blockIdx.x * blockDim.x + threadIdx.x;
    const int stride = gridDim.x * blockDim.x;
    const float2* s2 = (const float2*)src;
    __nv_bfloat162* h2 = (__nv_bfloat162*)hi;
    __nv_bfloat162* l2 = (__nv_bfloat162*)lo;
    for (int i = idx; i < n2; i += stride) {
        const float2 x = s2[i];
        const __nv_bfloat16 h0 = __float2bfloat16(x.x);
        const __nv_bfloat16 h1 = __float2bfloat16(x.y);
        __nv_bfloat162 hh; hh.x = h0; hh.y = h1;
        __nv_bfloat162 ll;
        ll.x = __float2bfloat16(x.x - __bfloat162float(h0));
        ll.y = __float2bfloat16(x.y - __bfloat162float(h1));
        h2[i] = hh;
        l2[i] = ll;
    }
}

// All 4 weights in one launch (blockIdx.y = weight index)
__global__ void __launch_bounds__(256) convert_w_kernel(
    const float* __restrict__ w0, const float* __restrict__ w1,
    const float* __restrict__ w2, const float* __restrict__ w3)
{
    const int wsel = blockIdx.y;
    const float* src = (wsel == 0) ? w0 : (wsel == 1) ? w1 : (wsel == 2) ? w2 : w3;
    __nv_bfloat162* h2 = (__nv_bfloat162*)(g_whi + (size_t)wsel * D_ * D_);
    __nv_bfloat162* l2 = (__nv_bfloat162*)(g_wlo + (size_t)wsel * D_ * D_);
    const float2* s2 = (const float2*)src;
    const int n2 = (D_ * D_) / 2;
    const int idx = blockIdx.x * blockDim.x + threadIdx.x;
    const int stride = gridDim.x * blockDim.x;
    for (int i = idx; i < n2; i += stride) {
        const float2 x = s2[i];
        const __nv_bfloat16 h0 = __float2bfloat16(x.x);
        const __nv_bfloat16 h1 = __float2bfloat16(x.y);
        __nv_bfloat162 hh; hh.x = h0; hh.y = h1;
        __nv_bfloat162 ll;
        ll.x = __float2bfloat16(x.x - __bfloat162float(h0));
        ll.y = __float2bfloat16(x.y - __bfloat162float(h1));
        h2[i] = hh;
        l2[i] = ll;
    }
}

// ---------------------------------------------------------------------------
// Tensor-core projection GEMM (unchanged)
// ---------------------------------------------------------------------------
#define GK 32
#define NKCH (D_ / GK)
#define ROWB 80
#define TILEB (128 * ROWB)
#define ABUF_HI 0
#define ABUF_LO TILEB
#define BBUF_HI (2 * TILEB)
#define BBUF_LO (3 * TILEB)
#define BUFB (4 * TILEB)
#define GEMM_SMEM (2 * BUFB)

__global__ void __launch_bounds__(256, 1) proj_mma_kernel(
    const float* __restrict__ bq, const float* __restrict__ bk,
    const float* __restrict__ bv, const float* __restrict__ ba)
{
    extern __shared__ __align__(16) char smem[];
    const uint32_t sbase = smem_u32(smem);

    const int pz = blockIdx.z;
    const float* bias;
    float* out;
    int act;
    if (pz == 0)      { bias = bq; out = g_q; act = 1; }
    else if (pz == 1) { bias = bk; out = g_k; act = 1; }
    else if (pz == 2) { bias = bv; out = g_v; act = 0; }
    else              { bias = ba; out = g_a; act = 2; }

    const int tid = threadIdx.x;
    const int w = tid >> 5;
    const int l = tid & 31;
    const int wm = w >> 2;
    const int wn = w & 3;

    const int mBase = blockIdx.y * 128;
    const int nBase = blockIdx.x * 128;

    const __nv_bfloat16* Whi = g_whi + (size_t)pz * D_ * D_;
    const __nv_bfloat16* Wlo = g_wlo + (size_t)pz * D_ * D_;

    const int slot0 = tid;
    const int slot1 = tid + 256;
    const int r0s = slot0 >> 2, s0s = slot0 & 3;
    const int r1s = slot1 >> 2, s1s = slot1 & 3;

    auto load_chunk = [&](int buf, int kc) {
        const uint32_t sb = sbase + buf * BUFB;
        const int k0 = kc * GK;
        {
            const size_t ga = (size_t)(mBase + r0s) * D_ + k0 + s0s * 8;
            const size_t gb = (size_t)(nBase + r0s) * D_ + k0 + s0s * 8;
            const uint32_t so = r0s * ROWB + s0s * 16;
            cp16(sb + ABUF_HI + so, g_xhi + ga);
            cp16(sb + ABUF_LO + so, g_xlo + ga);
            cp16(sb + BBUF_HI + so, Whi + gb);
            cp16(sb + BBUF_LO + so, Wlo + gb);
        }
        {
            const size_t ga = (size_t)(mBase + r1s) * D_ + k0 + s1s * 8;
            const size_t gb = (size_t)(nBase + r1s) * D_ + k0 + s1s * 8;
            const uint32_t so = r1s * ROWB + s1s * 16;
            cp16(sb + ABUF_HI + so, g_xhi + ga);
            cp16(sb + ABUF_LO + so, g_xlo + ga);
            cp16(sb + BBUF_HI + so, Whi + gb);
            cp16(sb + BBUF_LO + so, Wlo + gb);
        }
        asm volatile("cp.async.commit_group;");
    };

    float acc[4][4][4];
#pragma unroll
    for (int i = 0; i < 4; ++i)
#pragma unroll
        for (int j = 0; j < 4; ++j)
#pragma unroll
            for (int e = 0; e < 4; ++e) acc[i][j][e] = 0.0f;

    const int lrow = l & 15;
    const int lcol16 = (l >> 4) & 1;

    load_chunk(0, 0);

#pragma unroll 1
    for (int kc = 0; kc < NKCH; ++kc) {
        const int buf = kc & 1;
        if (kc + 1 < NKCH) {
            load_chunk(buf ^ 1, kc + 1);
            asm volatile("cp.async.wait_group 1;");
        } else {
            asm volatile("cp.async.wait_group 0;");
        }
        __syncthreads();

        const uint32_t sb = sbase + buf * BUFB;
#pragma unroll
        for (int kh = 0; kh < 2; ++kh) {
            const uint32_t coff = kh * 32 + lcol16 * 16;
            uint32_t ah[4][4], al[4][4];
#pragma unroll
            for (int mt = 0; mt < 4; ++mt) {
                const uint32_t ra = (wm * 64 + mt * 16 + lrow) * ROWB + coff;
                ldsm4(ah[mt], sb + ABUF_HI + ra);
                ldsm4(al[mt], sb + ABUF_LO + ra);
            }
            uint32_t bh[2][4], bl[2][4];
#pragma unroll
            for (int bt = 0; bt < 2; ++bt) {
                const uint32_t rb = (wn * 32 + bt * 16 + lrow) * ROWB + coff;
                ldsm4(bh[bt], sb + BBUF_HI + rb);
                ldsm4(bl[bt], sb + BBUF_LO + rb);
            }
#pragma unroll
            for (int mt = 0; mt < 4; ++mt)
#pragma unroll
                for (int nt = 0; nt < 4; ++nt) {
                    const int bt = nt >> 1;
                    const int hf = nt & 1;
                    mma16816(acc[mt][nt], ah[mt], bh[bt][hf], bh[bt][hf + 2]);
                    mma16816(acc[mt][nt], ah[mt], bl[bt][hf], bl[bt][hf + 2]);
                    mma16816(acc[mt][nt], al[mt], bh[bt][hf], bh[bt][hf + 2]);
                }
        }
        __syncthreads();
    }

#pragma unroll
    for (int nt = 0; nt < 4; ++nt) {
        const int col = nBase + wn * 32 + nt * 8 + 2 * (l & 3);
        const float2 b2 = *(const float2*)(bias + col);
#pragma unroll
        for (int mt = 0; mt < 4; ++mt) {
            const int row = mBase + wm * 64 + mt * 16 + (l >> 2);
            float2 r0, r1;
            r0.x = act_apply(acc[mt][nt][0] + b2.x, act);
            r0.y = act_apply(acc[mt][nt][1] + b2.y, act);
            r1.x = act_apply(acc[mt][nt][2] + b2.x, act);
            r1.y = act_apply(acc[mt][nt][3] + b2.y, act);
            *(float2*)(out + (size_t)row * D_ + col) = r0;
            *(float2*)(out + (size_t)(row + 8) * D_ + col) = r1;
        }
    }
}

// ---------------------------------------------------------------------------
// Chunked scan — NAMED-REGISTER state (S0..S15, no arrays, no dynamic index),
// pp-loop written as 4 explicit groups of 4 with compiler barriers between
// groups to bound ptxas's load-hoisting window (prevents the r7 spill storm).
// ---------------------------------------------------------------------------
#define SM_QTP  0
#define SM_KTP  (SM_QTP + 256*36)
#define SM_ACP  (SM_KTP + 256*36)
#define SM_V    (SM_ACP + 512)
#define SM_PART (SM_V + 512)
#define SM_DEN  (SM_PART + 16*32*17)
#define SM_FLOATS (SM_DEN + 512*17)
#define SCAN_SMEM_BYTES (SM_FLOATS * 4)

// One chunk-step for i-pair (w*16+PP), state register S.
#define SCAN_STEP(PP, S)                                                      \
    {                                                                         \
        const float* kb_ = sKtp + (w * 16 + (PP)) * 36 + th * 16;             \
        const float* qb_ = sQtp + (w * 16 + (PP)) * 36 + th * 16;             \
        const ulonglong2 k01 = *(const ulonglong2*)(kb_ + 0);                 \
        const ulonglong2 k23 = *(const ulonglong2*)(kb_ + 4);                 \
        const ulonglong2 k45 = *(const ulonglong2*)(kb_ + 8);                 \
        const ulonglong2 k67 = *(const ulonglong2*)(kb_ + 12);                \
        const ulonglong2 q01 = *(const ulonglong2*)(qb_ + 0);                 \
        const ulonglong2 q23 = *(const ulonglong2*)(qb_ + 4);                 \
        const ulonglong2 q45 = *(const ulonglong2*)(qb_ + 8);                 \
        const ulonglong2 q67 = *(const ulonglong2*)(qb_ + 12);                \
        S = fma2(k01.x, vd0, S); n0 = fma2(q01.x, S, n0);                     \
        S = fma2(k01.y, vd1, S); n1 = fma2(q01.y, S, n1);                     \
        S = fma2(k23.x, vd2, S); n2 = fma2(q23.x, S, n2);                     \
        S = fma2(k23.y, vd3, S); n3 = fma2(q23.y, S, n3);                     \
        S = fma2(k45.x, vd4, S); n4 = fma2(q45.x, S, n4);                     \
        S = fma2(k45.y, vd5, S); n5 = fma2(q45.y, S, n5);                     \
        S = fma2(k67.x, vd6, S); n6 = fma2(q67.x, S, n6);                     \
        S = fma2(k67.y, vd7, S); n7 = fma2(q67.y, S, n7);                     \
    }

#define SCHED_FENCE() asm volatile("" ::: "memory")

__global__ void __launch_bounds__(512, 1) scan_chunk_kernel(float* __restrict__ y)
{
    extern __shared__ __align__(16) float sm[];
    float* sQtp = sm + SM_QTP;
    float* sKtp = sm + SM_KTP;
    float* sACp = sm + SM_ACP;
    float* sV   = sm + SM_V;
    float* sPart= sm + SM_PART;
    float* sDen = sm + SM_DEN;

    const int b = blockIdx.y;
    const int jbase = blockIdx.x * 32;
    const int tid = threadIdx.x;
    const int w = tid >> 5;
    const int c = tid & 31;

    const float* gq = g_q + (size_t)b * S_ * D_;
    const float* gk = g_k + (size_t)b * S_ * D_;
    const float* gv = g_v + (size_t)b * S_ * D_;
    const float* ga = g_a + (size_t)b * S_ * D_;
    float* gy = y + (size_t)b * S_ * D_;

    // Named state registers: s[:, jbase+c] for i-pairs w*16 .. w*16+15
    u64 S0 = 0, S1 = 0, S2 = 0, S3 = 0, S4 = 0, S5 = 0, S6 = 0, S7 = 0;
    u64 S8 = 0, S9 = 0, S10 = 0, S11 = 0, S12 = 0, S13 = 0, S14 = 0, S15 = 0;
    float zreg = 0.0f;

    const int i_ = tid;
    const int p_ = i_ >> 1;
    const int hv_ = i_ & 1;

    {
        const int tpf = c & 15;
        const size_t roff = (size_t)tpf * D_ + w * 32;
        if (c < 16) {
            asm volatile("prefetch.global.L2 [%0];" :: "l"(gq + roff));
            asm volatile("prefetch.global.L2 [%0];" :: "l"(ga + roff));
        } else {
            asm volatile("prefetch.global.L2 [%0];" :: "l"(gk + roff));
            if (w == 0)
                asm volatile("prefetch.global.L2 [%0];"
                             :: "l"(gv + (size_t)tpf * D_ + jbase));
        }
    }

#pragma unroll 1
    for (int ch = 0; ch < NCH_; ++ch) {
        const int t0 = ch * C_;

        __syncthreads();   // B0

        // ---------------- stage2 ----------------
        {
            float av[16], qv[16], kv[16];
#pragma unroll
            for (int t = 0; t < 16; ++t) av[t] = ga[(size_t)(t0 + t) * D_ + i_];
#pragma unroll
            for (int t = 0; t < 16; ++t) qv[t] = gq[(size_t)(t0 + t) * D_ + i_];
#pragma unroll
            for (int t = 0; t < 16; ++t) kv[t] = gk[(size_t)(t0 + t) * D_ + i_];

            float A[16], invA[16];
            A[0] = av[0];
#pragma unroll
            for (int t = 1; t < 16; ++t) A[t] = A[t - 1] * av[t];
            invA[15] = __frcp_rn(A[15]);
#pragma unroll
            for (int t = 15; t >= 1; --t) invA[t - 1] = invA[t] * av[t];

            float zu = zreg;
#pragma unroll
            for (int t = 0; t < 16; ++t) {
                const float qt = qv[t] * A[t];
                const float kt = kv[t] * invA[t];
                zu += kt;
                sDen[i_ * 17 + t] = qt * zu;
                sQtp[p_ * 36 + t * 2 + hv_] = qt;
                sKtp[p_ * 36 + t * 2 + hv_] = kt;
            }
            zreg = A[15] * zu;
            sACp[p_ * 2 + hv_] = A[15];
        }

        if (tid < 128) {
            const int tv = tid >> 3;
            const int c4 = (tid & 7) << 2;
            const float4 vv = *(const float4*)(gv + (size_t)(t0 + tv) * D_ + jbase + c4);
            *(float4*)&sV[tv * 32 + c4] = vv;
        }

        __syncthreads();   // B1

        if (ch + 1 < NCH_) {
            const int tpf = c & 15;
            const size_t roff = (size_t)(t0 + 16 + tpf) * D_ + w * 32;
            if (c < 16) {
                asm volatile("prefetch.global.L2 [%0];" :: "l"(gq + roff));
                asm volatile("prefetch.global.L2 [%0];" :: "l"(ga + roff));
            } else {
                asm volatile("prefetch.global.L2 [%0];" :: "l"(gk + roff));
                if (w == 0)
                    asm volatile("prefetch.global.L2 [%0];"
                                 :: "l"(gv + (size_t)(t0 + 16 + tpf) * D_ + jbase));
            }
        }

        // ---------------- main loop (named registers, grouped) ----------------
#pragma unroll
        for (int th = 0; th < 2; ++th) {
            u64 vd0, vd1, vd2, vd3, vd4, vd5, vd6, vd7;
            {
                const float* vb = sV + th * 8 * 32 + c;
                float v;
                v = vb[0 * 32];  vd0 = pack2(v, v);
                v = vb[1 * 32];  vd1 = pack2(v, v);
                v = vb[2 * 32];  vd2 = pack2(v, v);
                v = vb[3 * 32];  vd3 = pack2(v, v);
                v = vb[4 * 32];  vd4 = pack2(v, v);
                v = vb[5 * 32];  vd5 = pack2(v, v);
                v = vb[6 * 32];  vd6 = pack2(v, v);
                v = vb[7 * 32];  vd7 = pack2(v, v);
            }
            u64 n0 = 0, n1 = 0, n2 = 0, n3 = 0, n4 = 0, n5 = 0, n6 = 0, n7 = 0;

            SCAN_STEP(0, S0)  SCAN_STEP(1, S1)  SCAN_STEP(2, S2)  SCAN_STEP(3, S3)
            SCHED_FENCE();
            SCAN_STEP(4, S4)  SCAN_STEP(5, S5)  SCAN_STEP(6, S6)  SCAN_STEP(7, S7)
            SCHED_FENCE();
            SCAN_STEP(8, S8)  SCAN_STEP(9, S9)  SCAN_STEP(10, S10) SCAN_STEP(11, S11)
            SCHED_FENCE();
            SCAN_STEP(12, S12) SCAN_STEP(13, S13) SCAN_STEP(14, S14) SCAN_STEP(15, S15)
            SCHED_FENCE();

            // write numerator partials: part[t][c][w]
            {
                float lo, hi;
                float* pb = sPart + (th * 8 * 32 + c) * 17 + w;
                unpack2(n0, lo, hi); pb[0 * 32 * 17] = lo + hi;
                unpack2(n1, lo, hi); pb[1 * 32 * 17] = lo + hi;
                unpack2(n2, lo, hi); pb[2 * 32 * 17] = lo + hi;
                unpack2(n3, lo, hi); pb[3 * 32 * 17] = lo + hi;
                unpack2(n4, lo, hi); pb[4 * 32 * 17] = lo + hi;
                unpack2(n5, lo, hi); pb[5 * 32 * 17] = lo + hi;
                unpack2(n6, lo, hi); pb[6 * 32 * 17] = lo + hi;
                unpack2(n7, lo, hi); pb[7 * 32 * 17] = lo + hi;
            }
        }

        // end-of-chunk state scale: s *= A_{C-1}
        {
            const u64* ac = (const u64*)(sACp + w * 16 * 2);
            S0  = mul2(S0,  ac[0]);  S1  = mul2(S1,  ac[1]);
            S2  = mul2(S2,  ac[2]);  S3  = mul2(S3,  ac[3]);
            S4  = mul2(S4,  ac[4]);  S5  = mul2(S5,  ac[5]);
            S6  = mul2(S6,  ac[6]);  S7  = mul2(S7,  ac[7]);
            S8  = mul2(S8,  ac[8]);  S9  = mul2(S9,  ac[9]);
            S10 = mul2(S10, ac[10]); S11 = mul2(S11, ac[11]);
            S12 = mul2(S12, ac[12]); S13 = mul2(S13, ac[13]);
            S14 = mul2(S14, ac[14]); S15 = mul2(S15, ac[15]);
        }

        __syncthreads();   // B2

        // ---------------- reduce + output ----------------
        {
            const int t = w;
            float num = 0.0f;
            float dpart = 0.0f;
#pragma unroll
            for (int ww = 0; ww < 16; ++ww) {
                num   += sPart[(t * 32 + c) * 17 + ww];
                dpart += sDen[(ww * 32 + c) * 17 + t];
            }
#pragma unroll
            for (int off = 16; off; off >>= 1)
                dpart += __shfl_xor_sync(0xffffffffu, dpart, off);
            const float inv = 1.0f / (dpart + kEPS);
            gy[(size_t)(t0 + t) * D_ + jbase + c] = num * inv;
        }
    }
}

// ---------------------------------------------------------------------------
// Launch
// ---------------------------------------------------------------------------
extern "C" void kernel_launch(void* const* d_in, const int* in_sizes, int n_in,
                              void* d_out, int out_size)
{
    const float* x  = (const float*)d_in[0];
    const float* Wq = (const float*)d_in[1];
    const float* bq = (const float*)d_in[2];
    const float* Wk = (const float*)d_in[3];
    const float* bk = (const float*)d_in[4];
    const float* Wv = (const float*)d_in[5];
    const float* bv = (const float*)d_in[6];
    const float* Wa = (const float*)d_in[7];
    const float* ba = (const float*)d_in[8];
    float* y = (float*)d_out;

    static __nv_bfloat16 *p_xhi = nullptr, *p_xlo = nullptr;
    if (!p_xhi) {
        cudaGetSymbolAddress((void**)&p_xhi, g_xhi);
        cudaGetSymbolAddress((void**)&p_xlo, g_xlo);
    }

    // 1) fp32 -> bf16 hi/lo splits
    convert_split_kernel<<<2048, 256>>>(x, p_xhi, p_xlo, (M_TOT * D_) / 2);
    dim3 wgrid(64, 4);
    convert_w_kernel<<<wgrid, 256>>>(Wq, Wk, Wv, Wa);

    // 2) tensor-core projections
    cudaFuncSetAttribute(proj_mma_kernel,
                         cudaFuncAttributeMaxDynamicSharedMemorySize, GEMM_SMEM);
    dim3 ggrid(D_ / 128, M_TOT / 128, 4);
    proj_mma_kernel<<<ggrid, 256, GEMM_SMEM>>>(bq, bk, bv, ba);

    // 3) chunked scan
    cudaFuncSetAttribute(scan_chunk_kernel,
                         cudaFuncAttributeMaxDynamicSharedMemorySize,
                         SCAN_SMEM_BYTES);
    dim3 sgrid(D_ / 32, B_);
    scan_chunk_kernel<<<sgrid, 512, SCAN_SMEM_BYTES>>>(y);
}

// round 9
// speedup vs baseline: 1.6217x; 1.0017x over previous
#include <cuda_runtime.h>
#include <cuda_bf16.h>
#include <cstdint>
#include <cstddef>

// Problem constants
#define B_ 8
#define S_ 4096
#define D_ 512
#define C_ 16                 // chunk length
#define NCH_ (S_ / C_)        // 256 chunks
#define M_TOT (B_ * S_)       // 32768

static __device__ __constant__ float kEPS = 1e-6f;

// ---------------------------------------------------------------------------
// Scratch (device globals: no allocation allowed)
// ---------------------------------------------------------------------------
__device__ float g_q[(size_t)B_ * S_ * D_];
__device__ float g_k[(size_t)B_ * S_ * D_];
__device__ float g_v[(size_t)B_ * S_ * D_];
__device__ float g_a[(size_t)B_ * S_ * D_];

// bf16 hi/lo split operands for tensor-core projections
__device__ __nv_bfloat16 g_xhi[(size_t)M_TOT * D_];
__device__ __nv_bfloat16 g_xlo[(size_t)M_TOT * D_];
__device__ __nv_bfloat16 g_whi[4 * D_ * D_];
__device__ __nv_bfloat16 g_wlo[4 * D_ * D_];

// ---------------------------------------------------------------------------
// f32x2 packed-math helpers (scan)
// ---------------------------------------------------------------------------
typedef unsigned long long u64;

__device__ __forceinline__ u64 pack2(float lo, float hi) {
    u64 r;
    asm("mov.b64 %0, {%1, %2};" : "=l"(r) : "f"(lo), "f"(hi));
    return r;
}
__device__ __forceinline__ void unpack2(u64 v, float& lo, float& hi) {
    asm("mov.b64 {%0, %1}, %2;" : "=f"(lo), "=f"(hi) : "l"(v));
}
__device__ __forceinline__ u64 fma2(u64 a, u64 b, u64 c) {
    u64 d;
    asm("fma.rn.f32x2 %0, %1, %2, %3;" : "=l"(d) : "l"(a), "l"(b), "l"(c));
    return d;
}
__device__ __forceinline__ u64 mul2(u64 a, u64 b) {
    u64 d;
    asm("mul.rn.f32x2 %0, %1, %2;" : "=l"(d) : "l"(a), "l"(b));
    return d;
}

// ---------------------------------------------------------------------------
// Tensor-core helpers
// ---------------------------------------------------------------------------
__device__ __forceinline__ uint32_t smem_u32(const void* p) {
    uint32_t a;
    asm("{ .reg .u64 t; cvta.to.shared.u64 t, %1; cvt.u32.u64 %0, t; }"
        : "=r"(a) : "l"(p));
    return a;
}
__device__ __forceinline__ void ldsm4(uint32_t* r, uint32_t addr) {
    asm volatile("ldmatrix.sync.aligned.m8n8.x4.shared.b16 {%0,%1,%2,%3}, [%4];"
                 : "=r"(r[0]), "=r"(r[1]), "=r"(r[2]), "=r"(r[3]) : "r"(addr));
}
__device__ __forceinline__ void mma16816(float* c, const uint32_t* a,
                                         uint32_t b0, uint32_t b1) {
    asm volatile(
        "mma.sync.aligned.m16n8k16.row.col.f32.bf16.bf16.f32 "
        "{%0,%1,%2,%3}, {%4,%5,%6,%7}, {%8,%9}, {%0,%1,%2,%3};"
        : "+f"(c[0]), "+f"(c[1]), "+f"(c[2]), "+f"(c[3])
        : "r"(a[0]), "r"(a[1]), "r"(a[2]), "r"(a[3]), "r"(b0), "r"(b1));
}
__device__ __forceinline__ void cp16(uint32_t saddr, const void* g) {
    asm volatile("cp.async.cg.shared.global [%0], [%1], 16;"
                 :: "r"(saddr), "l"(g));
}

__device__ __forceinline__ float act_apply(float x, int act) {
    if (act == 1) return fmaxf(x, 0.0f);               // relu
    if (act == 2) return 1.0f / (1.0f + __expf(-x));   // sigmoid
    return x;
}

// ---------------------------------------------------------------------------
// fp32 -> bf16 hi/lo split (x = hi + lo to ~2^-16 rel)
// ---------------------------------------------------------------------------
__global__ void __launch_bounds__(256) convert_split_kernel(
    const float* __restrict__ src,
    __nv_bfloat16* __restrict__ hi,
    __nv_bfloat16* __restrict__ lo, int n2)
{
    const int idx = blockIdx.x * blockDim.x + threadIdx.x;
    const int stride = gridDim.x * blockDim.x;
    const float2* s2 = (const float2*)src;
    __nv_bfloat162* h2 = (__nv_bfloat162*)hi;
    __nv_bfloat162* l2 = (__nv_bfloat162*)lo;
    for (int i = idx; i < n2; i += stride) {
        const float2 x = s2[i];
        const __nv_bfloat16 h0 = __float2bfloat16(x.x);
        const __nv_bfloat16 h1 = __float2bfloat16(x.y);
        __nv_bfloat162 hh; hh.x = h0; hh.y = h1;
        __nv_bfloat162 ll;
        ll.x = __float2bfloat16(x.x - __bfloat162float(h0));
        ll.y = __float2bfloat16(x.y - __bfloat162float(h1));
        h2[i] = hh;
        l2[i] = ll;
    }
}

// All 4 weights in one launch (blockIdx.y = weight index)
__global__ void __launch_bounds__(256) convert_w_kernel(
    const float* __restrict__ w0, const float* __restrict__ w1,
    const float* __restrict__ w2, const float* __restrict__ w3)
{
    const int wsel = blockIdx.y;
    const float* src = (wsel == 0) ? w0 : (wsel == 1) ? w1 : (wsel == 2) ? w2 : w3;
    __nv_bfloat162* h2 = (__nv_bfloat162*)(g_whi + (size_t)wsel * D_ * D_);
    __nv_bfloat162* l2 = (__nv_bfloat162*)(g_wlo + (size_t)wsel * D_ * D_);
    const float2* s2 = (const float2*)src;
    const int n2 = (D_ * D_) / 2;
    const int idx = blockIdx.x * blockDim.x + threadIdx.x;
    const int stride = gridDim.x * blockDim.x;
    for (int i = idx; i < n2; i += stride) {
        const float2 x = s2[i];
        const __nv_bfloat16 h0 = __float2bfloat16(x.x);
        const __nv_bfloat16 h1 = __float2bfloat16(x.y);
        __nv_bfloat162 hh; hh.x = h0; hh.y = h1;
        __nv_bfloat162 ll;
        ll.x = __float2bfloat16(x.x - __bfloat162float(h0));
        ll.y = __float2bfloat16(x.y - __bfloat162float(h1));
        h2[i] = hh;
        l2[i] = ll;
    }
}

// ---------------------------------------------------------------------------
// Tensor-core projection GEMM (unchanged)
// ---------------------------------------------------------------------------
#define GK 32
#define NKCH (D_ / GK)
#define ROWB 80
#define TILEB (128 * ROWB)
#define ABUF_HI 0
#define ABUF_LO TILEB
#define BBUF_HI (2 * TILEB)
#define BBUF_LO (3 * TILEB)
#define BUFB (4 * TILEB)
#define GEMM_SMEM (2 * BUFB)

__global__ void __launch_bounds__(256, 1) proj_mma_kernel(
    const float* __restrict__ bq, const float* __restrict__ bk,
    const float* __restrict__ bv, const float* __restrict__ ba)
{
    extern __shared__ __align__(16) char smem[];
    const uint32_t sbase = smem_u32(smem);

    const int pz = blockIdx.z;
    const float* bias;
    float* out;
    int act;
    if (pz == 0)      { bias = bq; out = g_q; act = 1; }
    else if (pz == 1) { bias = bk; out = g_k; act = 1; }
    else if (pz == 2) { bias = bv; out = g_v; act = 0; }
    else              { bias = ba; out = g_a; act = 2; }

    const int tid = threadIdx.x;
    const int w = tid >> 5;
    const int l = tid & 31;
    const int wm = w >> 2;
    const int wn = w & 3;

    const int mBase = blockIdx.y * 128;
    const int nBase = blockIdx.x * 128;

    const __nv_bfloat16* Whi = g_whi + (size_t)pz * D_ * D_;
    const __nv_bfloat16* Wlo = g_wlo + (size_t)pz * D_ * D_;

    const int slot0 = tid;
    const int slot1 = tid + 256;
    const int r0s = slot0 >> 2, s0s = slot0 & 3;
    const int r1s = slot1 >> 2, s1s = slot1 & 3;

    auto load_chunk = [&](int buf, int kc) {
        const uint32_t sb = sbase + buf * BUFB;
        const int k0 = kc * GK;
        {
            const size_t ga = (size_t)(mBase + r0s) * D_ + k0 + s0s * 8;
            const size_t gb = (size_t)(nBase + r0s) * D_ + k0 + s0s * 8;
            const uint32_t so = r0s * ROWB + s0s * 16;
            cp16(sb + ABUF_HI + so, g_xhi + ga);
            cp16(sb + ABUF_LO + so, g_xlo + ga);
            cp16(sb + BBUF_HI + so, Whi + gb);
            cp16(sb + BBUF_LO + so, Wlo + gb);
        }
        {
            const size_t ga = (size_t)(mBase + r1s) * D_ + k0 + s1s * 8;
            const size_t gb = (size_t)(nBase + r1s) * D_ + k0 + s1s * 8;
            const uint32_t so = r1s * ROWB + s1s * 16;
            cp16(sb + ABUF_HI + so, g_xhi + ga);
            cp16(sb + ABUF_LO + so, g_xlo + ga);
            cp16(sb + BBUF_HI + so, Whi + gb);
            cp16(sb + BBUF_LO + so, Wlo + gb);
        }
        asm volatile("cp.async.commit_group;");
    };

    float acc[4][4][4];
#pragma unroll
    for (int i = 0; i < 4; ++i)
#pragma unroll
        for (int j = 0; j < 4; ++j)
#pragma unroll
            for (int e = 0; e < 4; ++e) acc[i][j][e] = 0.0f;

    const int lrow = l & 15;
    const int lcol16 = (l >> 4) & 1;

    load_chunk(0, 0);

#pragma unroll 1
    for (int kc = 0; kc < NKCH; ++kc) {
        const int buf = kc & 1;
        if (kc + 1 < NKCH) {
            load_chunk(buf ^ 1, kc + 1);
            asm volatile("cp.async.wait_group 1;");
        } else {
            asm volatile("cp.async.wait_group 0;");
        }
        __syncthreads();

        const uint32_t sb = sbase + buf * BUFB;
#pragma unroll
        for (int kh = 0; kh < 2; ++kh) {
            const uint32_t coff = kh * 32 + lcol16 * 16;
            uint32_t ah[4][4], al[4][4];
#pragma unroll
            for (int mt = 0; mt < 4; ++mt) {
                const uint32_t ra = (wm * 64 + mt * 16 + lrow) * ROWB + coff;
                ldsm4(ah[mt], sb + ABUF_HI + ra);
                ldsm4(al[mt], sb + ABUF_LO + ra);
            }
            uint32_t bh[2][4], bl[2][4];
#pragma unroll
            for (int bt = 0; bt < 2; ++bt) {
                const uint32_t rb = (wn * 32 + bt * 16 + lrow) * ROWB + coff;
                ldsm4(bh[bt], sb + BBUF_HI + rb);
                ldsm4(bl[bt], sb + BBUF_LO + rb);
            }
#pragma unroll
            for (int mt = 0; mt < 4; ++mt)
#pragma unroll
                for (int nt = 0; nt < 4; ++nt) {
                    const int bt = nt >> 1;
                    const int hf = nt & 1;
                    mma16816(acc[mt][nt], ah[mt], bh[bt][hf], bh[bt][hf + 2]);
                    mma16816(acc[mt][nt], ah[mt], bl[bt][hf], bl[bt][hf + 2]);
                    mma16816(acc[mt][nt], al[mt], bh[bt][hf], bh[bt][hf + 2]);
                }
        }
        __syncthreads();
    }

#pragma unroll
    for (int nt = 0; nt < 4; ++nt) {
        const int col = nBase + wn * 32 + nt * 8 + 2 * (l & 3);
        const float2 b2 = *(const float2*)(bias + col);
#pragma unroll
        for (int mt = 0; mt < 4; ++mt) {
            const int row = mBase + wm * 64 + mt * 16 + (l >> 2);
            float2 r0, r1;
            r0.x = act_apply(acc[mt][nt][0] + b2.x, act);
            r0.y = act_apply(acc[mt][nt][1] + b2.y, act);
            r1.x = act_apply(acc[mt][nt][2] + b2.x, act);
            r1.y = act_apply(acc[mt][nt][3] + b2.y, act);
            *(float2*)(out + (size_t)row * D_ + col) = r0;
            *(float2*)(out + (size_t)(row + 8) * D_ + col) = r1;
        }
    }
}

// ---------------------------------------------------------------------------
// Chunked scan — named-register state; t split into 4 QUARTERS of 4 steps so
// the live window (S:32 + n:8 + vd:8 + 2-step temps:32 + misc) stays < 128
// regs and nothing spills. Fences every 2 steps bound ptxas hoisting.
// ---------------------------------------------------------------------------
#define SM_QTP  0
#define SM_KTP  (SM_QTP + 256*36)
#define SM_ACP  (SM_KTP + 256*36)
#define SM_V    (SM_ACP + 512)
#define SM_PART (SM_V + 512)
#define SM_DEN  (SM_PART + 16*32*17)
#define SM_FLOATS (SM_DEN + 512*17)
#define SCAN_SMEM_BYTES (SM_FLOATS * 4)

// One quarter-step (4 timesteps) for i-pair (w*16+PP), state register S.
#define SCAN_STEP4(PP, S)                                                     \
    {                                                                         \
        const float* kb_ = sKtp + (w * 16 + (PP)) * 36 + th * 8;              \
        const float* qb_ = sQtp + (w * 16 + (PP)) * 36 + th * 8;              \
        const ulonglong2 k01 = *(const ulonglong2*)(kb_ + 0);                 \
        const ulonglong2 k23 = *(const ulonglong2*)(kb_ + 4);                 \
        const ulonglong2 q01 = *(const ulonglong2*)(qb_ + 0);                 \
        const ulonglong2 q23 = *(const ulonglong2*)(qb_ + 4);                 \
        S = fma2(k01.x, vd0, S); n0 = fma2(q01.x, S, n0);                     \
        S = fma2(k01.y, vd1, S); n1 = fma2(q01.y, S, n1);                     \
        S = fma2(k23.x, vd2, S); n2 = fma2(q23.x, S, n2);                     \
        S = fma2(k23.y, vd3, S); n3 = fma2(q23.y, S, n3);                     \
    }

#define SCHED_FENCE() asm volatile("" ::: "memory")

__global__ void __launch_bounds__(512, 1) scan_chunk_kernel(float* __restrict__ y)
{
    extern __shared__ __align__(16) float sm[];
    float* sQtp = sm + SM_QTP;
    float* sKtp = sm + SM_KTP;
    float* sACp = sm + SM_ACP;
    float* sV   = sm + SM_V;
    float* sPart= sm + SM_PART;
    float* sDen = sm + SM_DEN;

    const int b = blockIdx.y;
    const int jbase = blockIdx.x * 32;
    const int tid = threadIdx.x;
    const int w = tid >> 5;
    const int c = tid & 31;

    const float* gq = g_q + (size_t)b * S_ * D_;
    const float* gk = g_k + (size_t)b * S_ * D_;
    const float* gv = g_v + (size_t)b * S_ * D_;
    const float* ga = g_a + (size_t)b * S_ * D_;
    float* gy = y + (size_t)b * S_ * D_;

    // Named state registers: s[:, jbase+c] for i-pairs w*16 .. w*16+15
    u64 S0 = 0, S1 = 0, S2 = 0, S3 = 0, S4 = 0, S5 = 0, S6 = 0, S7 = 0;
    u64 S8 = 0, S9 = 0, S10 = 0, S11 = 0, S12 = 0, S13 = 0, S14 = 0, S15 = 0;
    float zreg = 0.0f;

    const int i_ = tid;
    const int p_ = i_ >> 1;
    const int hv_ = i_ & 1;

    {
        const int tpf = c & 15;
        const size_t roff = (size_t)tpf * D_ + w * 32;
        if (c < 16) {
            asm volatile("prefetch.global.L2 [%0];" :: "l"(gq + roff));
            asm volatile("prefetch.global.L2 [%0];" :: "l"(ga + roff));
        } else {
            asm volatile("prefetch.global.L2 [%0];" :: "l"(gk + roff));
            if (w == 0)
                asm volatile("prefetch.global.L2 [%0];"
                             :: "l"(gv + (size_t)tpf * D_ + jbase));
        }
    }

#pragma unroll 1
    for (int ch = 0; ch < NCH_; ++ch) {
        const int t0 = ch * C_;

        __syncthreads();   // B0

        // ---------------- stage2 ----------------
        {
            float av[16], qv[16], kv[16];
#pragma unroll
            for (int t = 0; t < 16; ++t) av[t] = ga[(size_t)(t0 + t) * D_ + i_];
#pragma unroll
            for (int t = 0; t < 16; ++t) qv[t] = gq[(size_t)(t0 + t) * D_ + i_];
#pragma unroll
            for (int t = 0; t < 16; ++t) kv[t] = gk[(size_t)(t0 + t) * D_ + i_];

            float A[16], invA[16];
            A[0] = av[0];
#pragma unroll
            for (int t = 1; t < 16; ++t) A[t] = A[t - 1] * av[t];
            invA[15] = __frcp_rn(A[15]);
#pragma unroll
            for (int t = 15; t >= 1; --t) invA[t - 1] = invA[t] * av[t];

            float zu = zreg;
#pragma unroll
            for (int t = 0; t < 16; ++t) {
                const float qt = qv[t] * A[t];
                const float kt = kv[t] * invA[t];
                zu += kt;
                sDen[i_ * 17 + t] = qt * zu;
                sQtp[p_ * 36 + t * 2 + hv_] = qt;
                sKtp[p_ * 36 + t * 2 + hv_] = kt;
            }
            zreg = A[15] * zu;
            sACp[p_ * 2 + hv_] = A[15];
        }

        if (tid < 128) {
            const int tv = tid >> 3;
            const int c4 = (tid & 7) << 2;
            const float4 vv = *(const float4*)(gv + (size_t)(t0 + tv) * D_ + jbase + c4);
            *(float4*)&sV[tv * 32 + c4] = vv;
        }

        __syncthreads();   // B1

        if (ch + 1 < NCH_) {
            const int tpf = c & 15;
            const size_t roff = (size_t)(t0 + 16 + tpf) * D_ + w * 32;
            if (c < 16) {
                asm volatile("prefetch.global.L2 [%0];" :: "l"(gq + roff));
                asm volatile("prefetch.global.L2 [%0];" :: "l"(ga + roff));
            } else {
                asm volatile("prefetch.global.L2 [%0];" :: "l"(gk + roff));
                if (w == 0)
                    asm volatile("prefetch.global.L2 [%0];"
                                 :: "l"(gv + (size_t)(t0 + 16 + tpf) * D_ + jbase));
            }
        }

        // ---------------- main loop: 4 quarters of 4 timesteps ----------------
#pragma unroll
        for (int th = 0; th < 4; ++th) {
            u64 vd0, vd1, vd2, vd3;
            {
                const float* vb = sV + th * 4 * 32 + c;
                float v;
                v = vb[0 * 32];  vd0 = pack2(v, v);
                v = vb[1 * 32];  vd1 = pack2(v, v);
                v = vb[2 * 32];  vd2 = pack2(v, v);
                v = vb[3 * 32];  vd3 = pack2(v, v);
            }
            u64 n0 = 0, n1 = 0, n2 = 0, n3 = 0;

            SCAN_STEP4(0, S0)   SCAN_STEP4(1, S1)
            SCHED_FENCE();
            SCAN_STEP4(2, S2)   SCAN_STEP4(3, S3)
            SCHED_FENCE();
            SCAN_STEP4(4, S4)   SCAN_STEP4(5, S5)
            SCHED_FENCE();
            SCAN_STEP4(6, S6)   SCAN_STEP4(7, S7)
            SCHED_FENCE();
            SCAN_STEP4(8, S8)   SCAN_STEP4(9, S9)
            SCHED_FENCE();
            SCAN_STEP4(10, S10) SCAN_STEP4(11, S11)
            SCHED_FENCE();
            SCAN_STEP4(12, S12) SCAN_STEP4(13, S13)
            SCHED_FENCE();
            SCAN_STEP4(14, S14) SCAN_STEP4(15, S15)
            SCHED_FENCE();

            // write numerator partials: part[t][c][w]
            {
                float lo, hi;
                float* pb = sPart + (th * 4 * 32 + c) * 17 + w;
                unpack2(n0, lo, hi); pb[0 * 32 * 17] = lo + hi;
                unpack2(n1, lo, hi); pb[1 * 32 * 17] = lo + hi;
                unpack2(n2, lo, hi); pb[2 * 32 * 17] = lo + hi;
                unpack2(n3, lo, hi); pb[3 * 32 * 17] = lo + hi;
            }
        }

        // end-of-chunk state scale: s *= A_{C-1}
        {
            const u64* ac = (const u64*)(sACp + w * 16 * 2);
            S0  = mul2(S0,  ac[0]);  S1  = mul2(S1,  ac[1]);
            S2  = mul2(S2,  ac[2]);  S3  = mul2(S3,  ac[3]);
            S4  = mul2(S4,  ac[4]);  S5  = mul2(S5,  ac[5]);
            S6  = mul2(S6,  ac[6]);  S7  = mul2(S7,  ac[7]);
            S8  = mul2(S8,  ac[8]);  S9  = mul2(S9,  ac[9]);
            S10 = mul2(S10, ac[10]); S11 = mul2(S11, ac[11]);
            S12 = mul2(S12, ac[12]); S13 = mul2(S13, ac[13]);
            S14 = mul2(S14, ac[14]); S15 = mul2(S15, ac[15]);
        }

        __syncthreads();   // B2

        // ---------------- reduce + output ----------------
        {
            const int t = w;
            float num = 0.0f;
            float dpart = 0.0f;
#pragma unroll
            for (int ww = 0; ww < 16; ++ww) {
                num   += sPart[(t * 32 + c) * 17 + ww];
                dpart += sDen[(ww * 32 + c) * 17 + t];
            }
#pragma unroll
            for (int off = 16; off; off >>= 1)
                dpart += __shfl_xor_sync(0xffffffffu, dpart, off);
            const float inv = 1.0f / (dpart + kEPS);
            gy[(size_t)(t0 + t) * D_ + jbase + c] = num * inv;
        }
    }
}

// ---------------------------------------------------------------------------
// Launch
// ---------------------------------------------------------------------------
extern "C" void kernel_launch(void* const* d_in, const int* in_sizes, int n_in,
                              void* d_out, int out_size)
{
    const float* x  = (const float*)d_in[0];
    const float* Wq = (const float*)d_in[1];
    const float* bq = (const float*)d_in[2];
    const float* Wk = (const float*)d_in[3];
    const float* bk = (const float*)d_in[4];
    const float* Wv = (const float*)d_in[5];
    const float* bv = (const float*)d_in[6];
    const float* Wa = (const float*)d_in[7];
    const float* ba = (const float*)d_in[8];
    float* y = (float*)d_out;

    static __nv_bfloat16 *p_xhi = nullptr, *p_xlo = nullptr;
    if (!p_xhi) {
        cudaGetSymbolAddress((void**)&p_xhi, g_xhi);
        cudaGetSymbolAddress((void**)&p_xlo, g_xlo);
    }

    // 1) fp32 -> bf16 hi/lo splits
    convert_split_kernel<<<2048, 256>>>(x, p_xhi, p_xlo, (M_TOT * D_) / 2);
    dim3 wgrid(64, 4);
    convert_w_kernel<<<wgrid, 256>>>(Wq, Wk, Wv, Wa);

    // 2) tensor-core projections
    cudaFuncSetAttribute(proj_mma_kernel,
                         cudaFuncAttributeMaxDynamicSharedMemorySize, GEMM_SMEM);
    dim3 ggrid(D_ / 128, M_TOT / 128, 4);
    proj_mma_kernel<<<ggrid, 256, GEMM_SMEM>>>(bq, bk, bv, ba);

    // 3) chunked scan
    cudaFuncSetAttribute(scan_chunk_kernel,
                         cudaFuncAttributeMaxDynamicSharedMemorySize,
                         SCAN_SMEM_BYTES);
    dim3 sgrid(D_ / 32, B_);
    scan_chunk_kernel<<<sgrid, 512, SCAN_SMEM_BYTES>>>(y);
}

// round 11
// speedup vs baseline: 1.6233x; 1.0010x over previous
#include <cuda_runtime.h>
#include <cuda_bf16.h>
#include <cstdint>
#include <cstddef>

// Problem constants
#define B_ 8
#define S_ 4096
#define D_ 512
#define C_ 16                 // chunk length
#define NCH_ (S_ / C_)        // 256 chunks
#define M_TOT (B_ * S_)       // 32768

static __device__ __constant__ float kEPS = 1e-6f;

// ---------------------------------------------------------------------------
// Scratch (device globals: no allocation allowed)
// ---------------------------------------------------------------------------
__device__ float g_q[(size_t)B_ * S_ * D_];
__device__ float g_k[(size_t)B_ * S_ * D_];
__device__ float g_v[(size_t)B_ * S_ * D_];
__device__ float g_a[(size_t)B_ * S_ * D_];

// bf16 hi/lo split operands for tensor-core projections
__device__ __nv_bfloat16 g_xhi[(size_t)M_TOT * D_];
__device__ __nv_bfloat16 g_xlo[(size_t)M_TOT * D_];
__device__ __nv_bfloat16 g_whi[4 * D_ * D_];
__device__ __nv_bfloat16 g_wlo[4 * D_ * D_];

// ---------------------------------------------------------------------------
// f32x2 packed-math helpers (scan)
// ---------------------------------------------------------------------------
typedef unsigned long long u64;

__device__ __forceinline__ u64 pack2(float lo, float hi) {
    u64 r;
    asm("mov.b64 %0, {%1, %2};" : "=l"(r) : "f"(lo), "f"(hi));
    return r;
}
__device__ __forceinline__ void unpack2(u64 v, float& lo, float& hi) {
    asm("mov.b64 {%0, %1}, %2;" : "=f"(lo), "=f"(hi) : "l"(v));
}
__device__ __forceinline__ u64 fma2(u64 a, u64 b, u64 c) {
    u64 d;
    asm("fma.rn.f32x2 %0, %1, %2, %3;" : "=l"(d) : "l"(a), "l"(b), "l"(c));
    return d;
}
__device__ __forceinline__ u64 mul2(u64 a, u64 b) {
    u64 d;
    asm("mul.rn.f32x2 %0, %1, %2;" : "=l"(d) : "l"(a), "l"(b));
    return d;
}

// ---------------------------------------------------------------------------
// Tensor-core helpers
// ---------------------------------------------------------------------------
__device__ __forceinline__ uint32_t smem_u32(const void* p) {
    uint32_t a;
    asm("{ .reg .u64 t; cvta.to.shared.u64 t, %1; cvt.u32.u64 %0, t; }"
        : "=r"(a) : "l"(p));
    return a;
}
__device__ __forceinline__ void ldsm4(uint32_t* r, uint32_t addr) {
    asm volatile("ldmatrix.sync.aligned.m8n8.x4.shared.b16 {%0,%1,%2,%3}, [%4];"
                 : "=r"(r[0]), "=r"(r[1]), "=r"(r[2]), "=r"(r[3]) : "r"(addr));
}
__device__ __forceinline__ void mma16816(float* c, const uint32_t* a,
                                         uint32_t b0, uint32_t b1) {
    asm volatile(
        "mma.sync.aligned.m16n8k16.row.col.f32.bf16.bf16.f32 "
        "{%0,%1,%2,%3}, {%4,%5,%6,%7}, {%8,%9}, {%0,%1,%2,%3};"
        : "+f"(c[0]), "+f"(c[1]), "+f"(c[2]), "+f"(c[3])
        : "r"(a[0]), "r"(a[1]), "r"(a[2]), "r"(a[3]), "r"(b0), "r"(b1));
}
__device__ __forceinline__ void cp16(uint32_t saddr, const void* g) {
    asm volatile("cp.async.cg.shared.global [%0], [%1], 16;"
                 :: "r"(saddr), "l"(g));
}

__device__ __forceinline__ float act_apply(float x, int act) {
    if (act == 1) return fmaxf(x, 0.0f);               // relu
    if (act == 2) return 1.0f / (1.0f + __expf(-x));   // sigmoid
    return x;
}

// ---------------------------------------------------------------------------
// fp32 -> bf16 hi/lo split (x = hi + lo to ~2^-16 rel)
// ---------------------------------------------------------------------------
__global__ void __launch_bounds__(256) convert_split_kernel(
    const float* __restrict__ src,
    __nv_bfloat16* __restrict__ hi,
    __nv_bfloat16* __restrict__ lo, int n2)
{
    const int idx = blockIdx.x * blockDim.x + threadIdx.x;
    const int stride = gridDim.x * blockDim.x;
    const float2* s2 = (const float2*)src;
    __nv_bfloat162* h2 = (__nv_bfloat162*)hi;
    __nv_bfloat162* l2 = (__nv_bfloat162*)lo;
    for (int i = idx; i < n2; i += stride) {
        const float2 x = s2[i];
        const __nv_bfloat16 h0 = __float2bfloat16(x.x);
        const __nv_bfloat16 h1 = __float2bfloat16(x.y);
        __nv_bfloat162 hh; hh.x = h0; hh.y = h1;
        __nv_bfloat162 ll;
        ll.x = __float2bfloat16(x.x - __bfloat162float(h0));
        ll.y = __float2bfloat16(x.y - __bfloat162float(h1));
        h2[i] = hh;
        l2[i] = ll;
    }
}

// All 4 weights in one launch (blockIdx.y = weight index)
__global__ void __launch_bounds__(256) convert_w_kernel(
    const float* __restrict__ w0, const float* __restrict__ w1,
    const float* __restrict__ w2, const float* __restrict__ w3)
{
    const int wsel = blockIdx.y;
    const float* src = (wsel == 0) ? w0 : (wsel == 1) ? w1 : (wsel == 2) ? w2 : w3;
    __nv_bfloat162* h2 = (__nv_bfloat162*)(g_whi + (size_t)wsel * D_ * D_);
    __nv_bfloat162* l2 = (__nv_bfloat162*)(g_wlo + (size_t)wsel * D_ * D_);
    const float2* s2 = (const float2*)src;
    const int n2 = (D_ * D_) / 2;
    const int idx = blockIdx.x * blockDim.x + threadIdx.x;
    const int stride = gridDim.x * blockDim.x;
    for (int i = idx; i < n2; i += stride) {
        const float2 x = s2[i];
        const __nv_bfloat16 h0 = __float2bfloat16(x.x);
        const __nv_bfloat16 h1 = __float2bfloat16(x.y);
        __nv_bfloat162 hh; hh.x = h0; hh.y = h1;
        __nv_bfloat162 ll;
        ll.x = __float2bfloat16(x.x - __bfloat162float(h0));
        ll.y = __float2bfloat16(x.y - __bfloat162float(h1));
        h2[i] = hh;
        l2[i] = ll;
    }
}

// ---------------------------------------------------------------------------
// Tensor-core projection GEMM (unchanged)
// ---------------------------------------------------------------------------
#define GK 32
#define NKCH (D_ / GK)
#define ROWB 80
#define TILEB (128 * ROWB)
#define ABUF_HI 0
#define ABUF_LO TILEB
#define BBUF_HI (2 * TILEB)
#define BBUF_LO (3 * TILEB)
#define BUFB (4 * TILEB)
#define GEMM_SMEM (2 * BUFB)

__global__ void __launch_bounds__(256, 1) proj_mma_kernel(
    const float* __restrict__ bq, const float* __restrict__ bk,
    const float* __restrict__ bv, const float* __restrict__ ba)
{
    extern __shared__ __align__(16) char smem[];
    const uint32_t sbase = smem_u32(smem);

    const int pz = blockIdx.z;
    const float* bias;
    float* out;
    int act;
    if (pz == 0)      { bias = bq; out = g_q; act = 1; }
    else if (pz == 1) { bias = bk; out = g_k; act = 1; }
    else if (pz == 2) { bias = bv; out = g_v; act = 0; }
    else              { bias = ba; out = g_a; act = 2; }

    const int tid = threadIdx.x;
    const int w = tid >> 5;
    const int l = tid & 31;
    const int wm = w >> 2;
    const int wn = w & 3;

    const int mBase = blockIdx.y * 128;
    const int nBase = blockIdx.x * 128;

    const __nv_bfloat16* Whi = g_whi + (size_t)pz * D_ * D_;
    const __nv_bfloat16* Wlo = g_wlo + (size_t)pz * D_ * D_;

    const int slot0 = tid;
    const int slot1 = tid + 256;
    const int r0s = slot0 >> 2, s0s = slot0 & 3;
    const int r1s = slot1 >> 2, s1s = slot1 & 3;

    auto load_chunk = [&](int buf, int kc) {
        const uint32_t sb = sbase + buf * BUFB;
        const int k0 = kc * GK;
        {
            const size_t ga = (size_t)(mBase + r0s) * D_ + k0 + s0s * 8;
            const size_t gb = (size_t)(nBase + r0s) * D_ + k0 + s0s * 8;
            const uint32_t so = r0s * ROWB + s0s * 16;
            cp16(sb + ABUF_HI + so, g_xhi + ga);
            cp16(sb + ABUF_LO + so, g_xlo + ga);
            cp16(sb + BBUF_HI + so, Whi + gb);
            cp16(sb + BBUF_LO + so, Wlo + gb);
        }
        {
            const size_t ga = (size_t)(mBase + r1s) * D_ + k0 + s1s * 8;
            const size_t gb = (size_t)(nBase + r1s) * D_ + k0 + s1s * 8;
            const uint32_t so = r1s * ROWB + s1s * 16;
            cp16(sb + ABUF_HI + so, g_xhi + ga);
            cp16(sb + ABUF_LO + so, g_xlo + ga);
            cp16(sb + BBUF_HI + so, Whi + gb);
            cp16(sb + BBUF_LO + so, Wlo + gb);
        }
        asm volatile("cp.async.commit_group;");
    };

    float acc[4][4][4];
#pragma unroll
    for (int i = 0; i < 4; ++i)
#pragma unroll
        for (int j = 0; j < 4; ++j)
#pragma unroll
            for (int e = 0; e < 4; ++e) acc[i][j][e] = 0.0f;

    const int lrow = l & 15;
    const int lcol16 = (l >> 4) & 1;

    load_chunk(0, 0);

#pragma unroll 1
    for (int kc = 0; kc < NKCH; ++kc) {
        const int buf = kc & 1;
        if (kc + 1 < NKCH) {
            load_chunk(buf ^ 1, kc + 1);
            asm volatile("cp.async.wait_group 1;");
        } else {
            asm volatile("cp.async.wait_group 0;");
        }
        __syncthreads();

        const uint32_t sb = sbase + buf * BUFB;
#pragma unroll
        for (int kh = 0; kh < 2; ++kh) {
            const uint32_t coff = kh * 32 + lcol16 * 16;
            uint32_t ah[4][4], al[4][4];
#pragma unroll
            for (int mt = 0; mt < 4; ++mt) {
                const uint32_t ra = (wm * 64 + mt * 16 + lrow) * ROWB + coff;
                ldsm4(ah[mt], sb + ABUF_HI + ra);
                ldsm4(al[mt], sb + ABUF_LO + ra);
            }
            uint32_t bh[2][4], bl[2][4];
#pragma unroll
            for (int bt = 0; bt < 2; ++bt) {
                const uint32_t rb = (wn * 32 + bt * 16 + lrow) * ROWB + coff;
                ldsm4(bh[bt], sb + BBUF_HI + rb);
                ldsm4(bl[bt], sb + BBUF_LO + rb);
            }
#pragma unroll
            for (int mt = 0; mt < 4; ++mt)
#pragma unroll
                for (int nt = 0; nt < 4; ++nt) {
                    const int bt = nt >> 1;
                    const int hf = nt & 1;
                    mma16816(acc[mt][nt], ah[mt], bh[bt][hf], bh[bt][hf + 2]);
                    mma16816(acc[mt][nt], ah[mt], bl[bt][hf], bl[bt][hf + 2]);
                    mma16816(acc[mt][nt], al[mt], bh[bt][hf], bh[bt][hf + 2]);
                }
        }
        __syncthreads();
    }

#pragma unroll
    for (int nt = 0; nt < 4; ++nt) {
        const int col = nBase + wn * 32 + nt * 8 + 2 * (l & 3);
        const float2 b2 = *(const float2*)(bias + col);
#pragma unroll
        for (int mt = 0; mt < 4; ++mt) {
            const int row = mBase + wm * 64 + mt * 16 + (l >> 2);
            float2 r0, r1;
            r0.x = act_apply(acc[mt][nt][0] + b2.x, act);
            r0.y = act_apply(acc[mt][nt][1] + b2.y, act);
            r1.x = act_apply(acc[mt][nt][2] + b2.x, act);
            r1.y = act_apply(acc[mt][nt][3] + b2.y, act);
            *(float2*)(out + (size_t)row * D_ + col) = r0;
            *(float2*)(out + (size_t)(row + 8) * D_ + col) = r1;
        }
    }
}

// ---------------------------------------------------------------------------
// Chunked scan — named-register state; t split into 4 QUARTERS of 4 steps so
// the live window (S:32 + n:8 + vd:8 + 2-step temps:32 + misc) stays < 128
// regs and nothing spills. Fences every 2 steps bound ptxas hoisting.
// ---------------------------------------------------------------------------
#define SM_QTP  0
#define SM_KTP  (SM_QTP + 256*36)
#define SM_ACP  (SM_KTP + 256*36)
#define SM_V    (SM_ACP + 512)
#define SM_PART (SM_V + 512)
#define SM_DEN  (SM_PART + 16*32*17)
#define SM_FLOATS (SM_DEN + 512*17)
#define SCAN_SMEM_BYTES (SM_FLOATS * 4)

// One quarter-step (4 timesteps) for i-pair (w*16+PP), state register S.
#define SCAN_STEP4(PP, S)                                                     \
    {                                                                         \
        const float* kb_ = sKtp + (w * 16 + (PP)) * 36 + th * 8;              \
        const float* qb_ = sQtp + (w * 16 + (PP)) * 36 + th * 8;              \
        const ulonglong2 k01 = *(const ulonglong2*)(kb_ + 0);                 \
        const ulonglong2 k23 = *(const ulonglong2*)(kb_ + 4);                 \
        const ulonglong2 q01 = *(const ulonglong2*)(qb_ + 0);                 \
        const ulonglong2 q23 = *(const ulonglong2*)(qb_ + 4);                 \
        S = fma2(k01.x, vd0, S); n0 = fma2(q01.x, S, n0);                     \
        S = fma2(k01.y, vd1, S); n1 = fma2(q01.y, S, n1);                     \
        S = fma2(k23.x, vd2, S); n2 = fma2(q23.x, S, n2);                     \
        S = fma2(k23.y, vd3, S); n3 = fma2(q23.y, S, n3);                     \
    }

#define SCHED_FENCE() asm volatile("" ::: "memory")

__global__ void __launch_bounds__(512, 1) scan_chunk_kernel(float* __restrict__ y)
{
    extern __shared__ __align__(16) float sm[];
    float* sQtp = sm + SM_QTP;
    float* sKtp = sm + SM_KTP;
    float* sACp = sm + SM_ACP;
    float* sV   = sm + SM_V;
    float* sPart= sm + SM_PART;
    float* sDen = sm + SM_DEN;

    const int b = blockIdx.y;
    const int jbase = blockIdx.x * 32;
    const int tid = threadIdx.x;
    const int w = tid >> 5;
    const int c = tid & 31;

    const float* gq = g_q + (size_t)b * S_ * D_;
    const float* gk = g_k + (size_t)b * S_ * D_;
    const float* gv = g_v + (size_t)b * S_ * D_;
    const float* ga = g_a + (size_t)b * S_ * D_;
    float* gy = y + (size_t)b * S_ * D_;

    // Named state registers: s[:, jbase+c] for i-pairs w*16 .. w*16+15
    u64 S0 = 0, S1 = 0, S2 = 0, S3 = 0, S4 = 0, S5 = 0, S6 = 0, S7 = 0;
    u64 S8 = 0, S9 = 0, S10 = 0, S11 = 0, S12 = 0, S13 = 0, S14 = 0, S15 = 0;
    float zreg = 0.0f;

    const int i_ = tid;
    const int p_ = i_ >> 1;
    const int hv_ = i_ & 1;

    {
        const int tpf = c & 15;
        const size_t roff = (size_t)tpf * D_ + w * 32;
        if (c < 16) {
            asm volatile("prefetch.global.L2 [%0];" :: "l"(gq + roff));
            asm volatile("prefetch.global.L2 [%0];" :: "l"(ga + roff));
        } else {
            asm volatile("prefetch.global.L2 [%0];" :: "l"(gk + roff));
            if (w == 0)
                asm volatile("prefetch.global.L2 [%0];"
                             :: "l"(gv + (size_t)tpf * D_ + jbase));
        }
    }

#pragma unroll 1
    for (int ch = 0; ch < NCH_; ++ch) {
        const int t0 = ch * C_;

        __syncthreads();   // B0

        // ---------------- stage2 ----------------
        {
            float av[16], qv[16], kv[16];
#pragma unroll
            for (int t = 0; t < 16; ++t) av[t] = ga[(size_t)(t0 + t) * D_ + i_];
#pragma unroll
            for (int t = 0; t < 16; ++t) qv[t] = gq[(size_t)(t0 + t) * D_ + i_];
#pragma unroll
            for (int t = 0; t < 16; ++t) kv[t] = gk[(size_t)(t0 + t) * D_ + i_];

            float A[16], invA[16];
            A[0] = av[0];
#pragma unroll
            for (int t = 1; t < 16; ++t) A[t] = A[t - 1] * av[t];
            invA[15] = __frcp_rn(A[15]);
#pragma unroll
            for (int t = 15; t >= 1; --t) invA[t - 1] = invA[t] * av[t];

            float zu = zreg;
#pragma unroll
            for (int t = 0; t < 16; ++t) {
                const float qt = qv[t] * A[t];
                const float kt = kv[t] * invA[t];
                zu += kt;
                sDen[i_ * 17 + t] = qt * zu;
                sQtp[p_ * 36 + t * 2 + hv_] = qt;
                sKtp[p_ * 36 + t * 2 + hv_] = kt;
            }
            zreg = A[15] * zu;
            sACp[p_ * 2 + hv_] = A[15];
        }

        if (tid < 128) {
            const int tv = tid >> 3;
            const int c4 = (tid & 7) << 2;
            const float4 vv = *(const float4*)(gv + (size_t)(t0 + tv) * D_ + jbase + c4);
            *(float4*)&sV[tv * 32 + c4] = vv;
        }

        __syncthreads();   // B1

        if (ch + 1 < NCH_) {
            const int tpf = c & 15;
            const size_t roff = (size_t)(t0 + 16 + tpf) * D_ + w * 32;
            if (c < 16) {
                asm volatile("prefetch.global.L2 [%0];" :: "l"(gq + roff));
                asm volatile("prefetch.global.L2 [%0];" :: "l"(ga + roff));
            } else {
                asm volatile("prefetch.global.L2 [%0];" :: "l"(gk + roff));
                if (w == 0)
                    asm volatile("prefetch.global.L2 [%0];"
                                 :: "l"(gv + (size_t)(t0 + 16 + tpf) * D_ + jbase));
            }
        }

        // ---------------- main loop: 4 quarters of 4 timesteps ----------------
#pragma unroll
        for (int th = 0; th < 4; ++th) {
            u64 vd0, vd1, vd2, vd3;
            {
                const float* vb = sV + th * 4 * 32 + c;
                float v;
                v = vb[0 * 32];  vd0 = pack2(v, v);
                v = vb[1 * 32];  vd1 = pack2(v, v);
                v = vb[2 * 32];  vd2 = pack2(v, v);
                v = vb[3 * 32];  vd3 = pack2(v, v);
            }
            u64 n0 = 0, n1 = 0, n2 = 0, n3 = 0;

            SCAN_STEP4(0, S0)   SCAN_STEP4(1, S1)
            SCHED_FENCE();
            SCAN_STEP4(2, S2)   SCAN_STEP4(3, S3)
            SCHED_FENCE();
            SCAN_STEP4(4, S4)   SCAN_STEP4(5, S5)
            SCHED_FENCE();
            SCAN_STEP4(6, S6)   SCAN_STEP4(7, S7)
            SCHED_FENCE();
            SCAN_STEP4(8, S8)   SCAN_STEP4(9, S9)
            SCHED_FENCE();
            SCAN_STEP4(10, S10) SCAN_STEP4(11, S11)
            SCHED_FENCE();
            SCAN_STEP4(12, S12) SCAN_STEP4(13, S13)
            SCHED_FENCE();
            SCAN_STEP4(14, S14) SCAN_STEP4(15, S15)
            SCHED_FENCE();

            // write numerator partials: part[t][c][w]
            {
                float lo, hi;
                float* pb = sPart + (th * 4 * 32 + c) * 17 + w;
                unpack2(n0, lo, hi); pb[0 * 32 * 17] = lo + hi;
                unpack2(n1, lo, hi); pb[1 * 32 * 17] = lo + hi;
                unpack2(n2, lo, hi); pb[2 * 32 * 17] = lo + hi;
                unpack2(n3, lo, hi); pb[3 * 32 * 17] = lo + hi;
            }
        }

        // end-of-chunk state scale: s *= A_{C-1}
        {
            const u64* ac = (const u64*)(sACp + w * 16 * 2);
            S0  = mul2(S0,  ac[0]);  S1  = mul2(S1,  ac[1]);
            S2  = mul2(S2,  ac[2]);  S3  = mul2(S3,  ac[3]);
            S4  = mul2(S4,  ac[4]);  S5  = mul2(S5,  ac[5]);
            S6  = mul2(S6,  ac[6]);  S7  = mul2(S7,  ac[7]);
            S8  = mul2(S8,  ac[8]);  S9  = mul2(S9,  ac[9]);
            S10 = mul2(S10, ac[10]); S11 = mul2(S11, ac[11]);
            S12 = mul2(S12, ac[12]); S13 = mul2(S13, ac[13]);
            S14 = mul2(S14, ac[14]); S15 = mul2(S15, ac[15]);
        }

        __syncthreads();   // B2

        // ---------------- reduce + output ----------------
        {
            const int t = w;
            float num = 0.0f;
            float dpart = 0.0f;
#pragma unroll
            for (int ww = 0; ww < 16; ++ww) {
                num   += sPart[(t * 32 + c) * 17 + ww];
                dpart += sDen[(ww * 32 + c) * 17 + t];
            }
#pragma unroll
            for (int off = 16; off; off >>= 1)
                dpart += __shfl_xor_sync(0xffffffffu, dpart, off);
            const float inv = 1.0f / (dpart + kEPS);
            gy[(size_t)(t0 + t) * D_ + jbase + c] = num * inv;
        }
    }
}

// ---------------------------------------------------------------------------
// Launch
// ---------------------------------------------------------------------------
extern "C" void kernel_launch(void* const* d_in, const int* in_sizes, int n_in,
                              void* d_out, int out_size)
{
    const float* x  = (const float*)d_in[0];
    const float* Wq = (const float*)d_in[1];
    const float* bq = (const float*)d_in[2];
    const float* Wk = (const float*)d_in[3];
    const float* bk = (const float*)d_in[4];
    const float* Wv = (const float*)d_in[5];
    const float* bv = (const float*)d_in[6];
    const float* Wa = (const float*)d_in[7];
    const float* ba = (const float*)d_in[8];
    float* y = (float*)d_out;

    static __nv_bfloat16 *p_xhi = nullptr, *p_xlo = nullptr;
    if (!p_xhi) {
        cudaGetSymbolAddress((void**)&p_xhi, g_xhi);
        cudaGetSymbolAddress((void**)&p_xlo, g_xlo);
    }

    // 1) fp32 -> bf16 hi/lo splits
    convert_split_kernel<<<2048, 256>>>(x, p_xhi, p_xlo, (M_TOT * D_) / 2);
    dim3 wgrid(64, 4);
    convert_w_kernel<<<wgrid, 256>>>(Wq, Wk, Wv, Wa);

    // 2) tensor-core projections
    cudaFuncSetAttribute(proj_mma_kernel,
                         cudaFuncAttributeMaxDynamicSharedMemorySize, GEMM_SMEM);
    dim3 ggrid(D_ / 128, M_TOT / 128, 4);
    proj_mma_kernel<<<ggrid, 256, GEMM_SMEM>>>(bq, bk, bv, ba);

    // 3) chunked scan
    cudaFuncSetAttribute(scan_chunk_kernel,
                         cudaFuncAttributeMaxDynamicSharedMemorySize,
                         SCAN_SMEM_BYTES);
    dim3 sgrid(D_ / 32, B_);
    scan_chunk_kernel<<<sgrid, 512, SCAN_SMEM_BYTES>>>(y);
}

// round 12
// speedup vs baseline: 1.9759x; 1.2172x over previous
#include <cuda_runtime.h>
#include <cuda_bf16.h>
#include <cstdint>
#include <cstddef>

#define B_ 8
#define S_ 4096
#define D_ 512
#define C_ 16
#define NCH_ (S_ / C_)
#define M_TOT (B_ * S_)

static __device__ __constant__ float kEPS = 1e-6f;

__device__ float g_q[(size_t)B_ * S_ * D_];
__device__ float g_k[(size_t)B_ * S_ * D_];
__device__ float g_v[(size_t)B_ * S_ * D_];
__device__ float g_a[(size_t)B_ * S_ * D_];
__device__ __nv_bfloat16 g_xhi[(size_t)M_TOT * D_];
__device__ __nv_bfloat16 g_xlo[(size_t)M_TOT * D_];
__device__ __nv_bfloat16 g_whi[4 * D_ * D_];
__device__ __nv_bfloat16 g_wlo[4 * D_ * D_];

typedef uint32_t u32;

__device__ __forceinline__ uint32_t smem_u32(const void* p) {
    uint32_t a;
    asm("{ .reg .u64 t; cvta.to.shared.u64 t, %1; cvt.u32.u64 %0, t; }"
        : "=r"(a) : "l"(p));
    return a;
}
__device__ __forceinline__ void ldsm4(u32* r, u32 addr) {
    asm volatile("ldmatrix.sync.aligned.m8n8.x4.shared.b16 {%0,%1,%2,%3}, [%4];"
                 : "=r"(r[0]), "=r"(r[1]), "=r"(r[2]), "=r"(r[3]) : "r"(addr));
}
__device__ __forceinline__ void ldsm4t(u32* r, u32 addr) {
    asm volatile("ldmatrix.sync.aligned.m8n8.x4.trans.shared.b16 {%0,%1,%2,%3}, [%4];"
                 : "=r"(r[0]), "=r"(r[1]), "=r"(r[2]), "=r"(r[3]) : "r"(addr));
}
__device__ __forceinline__ u32 movmt(u32 a) {
    u32 d;
    asm volatile("movmatrix.sync.aligned.m8n8.trans.b16 %0, %1;" : "=r"(d) : "r"(a));
    return d;
}
__device__ __forceinline__ u32 bfpack(float lo, float hi) {
    u32 d;
    asm("cvt.rn.bf16x2.f32 %0, %1, %2;" : "=r"(d) : "f"(hi), "f"(lo));
    return d;
}
__device__ __forceinline__ float bfres(float x) {
    return x - __bfloat162float(__float2bfloat16(x));
}
__device__ __forceinline__ void mma16816(float* c, const u32* a, u32 b0, u32 b1) {
    asm volatile(
        "mma.sync.aligned.m16n8k16.row.col.f32.bf16.bf16.f32 "
        "{%0,%1,%2,%3}, {%4,%5,%6,%7}, {%8,%9}, {%0,%1,%2,%3};"
        : "+f"(c[0]), "+f"(c[1]), "+f"(c[2]), "+f"(c[3])
        : "r"(a[0]), "r"(a[1]), "r"(a[2]), "r"(a[3]), "r"(b0), "r"(b1));
}
__device__ __forceinline__ void cp16(u32 saddr, const void* g) {
    asm volatile("cp.async.cg.shared.global [%0], [%1], 16;" :: "r"(saddr), "l"(g));
}
__device__ __forceinline__ float act_apply(float x, int act) {
    if (act == 1) return fmaxf(x, 0.0f);
    if (act == 2) return 1.0f / (1.0f + __expf(-x));
    return x;
}

// -------------------- converts --------------------
__global__ void __launch_bounds__(256) convert_split_kernel(
    const float* __restrict__ src, __nv_bfloat16* __restrict__ hi,
    __nv_bfloat16* __restrict__ lo, int n2)
{
    const int idx = blockIdx.x * blockDim.x + threadIdx.x;
    const int stride = gridDim.x * blockDim.x;
    const float2* s2 = (const float2*)src;
    __nv_bfloat162* h2 = (__nv_bfloat162*)hi;
    __nv_bfloat162* l2 = (__nv_bfloat162*)lo;
    for (int i = idx; i < n2; i += stride) {
        const float2 x = s2[i];
        const __nv_bfloat16 h0 = __float2bfloat16(x.x);
        const __nv_bfloat16 h1 = __float2bfloat16(x.y);
        __nv_bfloat162 hh; hh.x = h0; hh.y = h1;
        __nv_bfloat162 ll;
        ll.x = __float2bfloat16(x.x - __bfloat162float(h0));
        ll.y = __float2bfloat16(x.y - __bfloat162float(h1));
        h2[i] = hh; l2[i] = ll;
    }
}

__global__ void __launch_bounds__(256) convert_w_kernel(
    const float* __restrict__ w0, const float* __restrict__ w1,
    const float* __restrict__ w2, const float* __restrict__ w3)
{
    const int wsel = blockIdx.y;
    const float* src = (wsel == 0) ? w0 : (wsel == 1) ? w1 : (wsel == 2) ? w2 : w3;
    __nv_bfloat162* h2 = (__nv_bfloat162*)(g_whi + (size_t)wsel * D_ * D_);
    __nv_bfloat162* l2 = (__nv_bfloat162*)(g_wlo + (size_t)wsel * D_ * D_);
    const float2* s2 = (const float2*)src;
    const int n2 = (D_ * D_) / 2;
    const int idx = blockIdx.x * blockDim.x + threadIdx.x;
    const int stride = gridDim.x * blockDim.x;
    for (int i = idx; i < n2; i += stride) {
        const float2 x = s2[i];
        const __nv_bfloat16 h0 = __float2bfloat16(x.x);
        const __nv_bfloat16 h1 = __float2bfloat16(x.y);
        __nv_bfloat162 hh; hh.x = h0; hh.y = h1;
        __nv_bfloat162 ll;
        ll.x = __float2bfloat16(x.x - __bfloat162float(h0));
        ll.y = __float2bfloat16(x.y - __bfloat162float(h1));
        h2[i] = hh; l2[i] = ll;
    }
}

// -------------------- projection GEMM (proven) --------------------
#define GK 32
#define NKCH (D_ / GK)
#define ROWB 80
#define TILEB (128 * ROWB)
#define ABUF_HI 0
#define ABUF_LO TILEB
#define BBUF_HI (2 * TILEB)
#define BBUF_LO (3 * TILEB)
#define BUFB (4 * TILEB)
#define GEMM_SMEM (2 * BUFB)

__global__ void __launch_bounds__(256, 1) proj_mma_kernel(
    const float* __restrict__ bq, const float* __restrict__ bk,
    const float* __restrict__ bv, const float* __restrict__ ba)
{
    extern __shared__ __align__(16) char smem[];
    const u32 sbase = smem_u32(smem);
    const int pz = blockIdx.z;
    const float* bias; float* out; int act;
    if (pz == 0)      { bias = bq; out = g_q; act = 1; }
    else if (pz == 1) { bias = bk; out = g_k; act = 1; }
    else if (pz == 2) { bias = bv; out = g_v; act = 0; }
    else              { bias = ba; out = g_a; act = 2; }

    const int tid = threadIdx.x, w = tid >> 5, l = tid & 31;
    const int wm = w >> 2, wn = w & 3;
    const int mBase = blockIdx.y * 128, nBase = blockIdx.x * 128;
    const __nv_bfloat16* Whi = g_whi + (size_t)pz * D_ * D_;
    const __nv_bfloat16* Wlo = g_wlo + (size_t)pz * D_ * D_;
    const int r0s = tid >> 2, s0s = tid & 3;
    const int r1s = (tid + 256) >> 2, s1s = tid & 3;

    auto load_chunk = [&](int buf, int kc) {
        const u32 sb = sbase + buf * BUFB;
        const int k0 = kc * GK;
        {
            const size_t ga = (size_t)(mBase + r0s) * D_ + k0 + s0s * 8;
            const size_t gb = (size_t)(nBase + r0s) * D_ + k0 + s0s * 8;
            const u32 so = r0s * ROWB + s0s * 16;
            cp16(sb + ABUF_HI + so, g_xhi + ga);
            cp16(sb + ABUF_LO + so, g_xlo + ga);
            cp16(sb + BBUF_HI + so, Whi + gb);
            cp16(sb + BBUF_LO + so, Wlo + gb);
        }
        {
            const size_t ga = (size_t)(mBase + r1s) * D_ + k0 + s1s * 8;
            const size_t gb = (size_t)(nBase + r1s) * D_ + k0 + s1s * 8;
            const u32 so = r1s * ROWB + s1s * 16;
            cp16(sb + ABUF_HI + so, g_xhi + ga);
            cp16(sb + ABUF_LO + so, g_xlo + ga);
            cp16(sb + BBUF_HI + so, Whi + gb);
            cp16(sb + BBUF_LO + so, Wlo + gb);
        }
        asm volatile("cp.async.commit_group;");
    };

    float acc[4][4][4];
#pragma unroll
    for (int i = 0; i < 4; ++i)
#pragma unroll
        for (int j = 0; j < 4; ++j)
#pragma unroll
            for (int e = 0; e < 4; ++e) acc[i][j][e] = 0.0f;

    const int lrow = l & 15, lcol16 = (l >> 4) & 1;
    load_chunk(0, 0);

#pragma unroll 1
    for (int kc = 0; kc < NKCH; ++kc) {
        const int buf = kc & 1;
        if (kc + 1 < NKCH) {
            load_chunk(buf ^ 1, kc + 1);
            asm volatile("cp.async.wait_group 1;");
        } else {
            asm volatile("cp.async.wait_group 0;");
        }
        __syncthreads();
        const u32 sb = sbase + buf * BUFB;
#pragma unroll
        for (int kh = 0; kh < 2; ++kh) {
            const u32 coff = kh * 32 + lcol16 * 16;
            u32 ah[4][4], al[4][4];
#pragma unroll
            for (int mt = 0; mt < 4; ++mt) {
                const u32 ra = (wm * 64 + mt * 16 + lrow) * ROWB + coff;
                ldsm4(ah[mt], sb + ABUF_HI + ra);
                ldsm4(al[mt], sb + ABUF_LO + ra);
            }
            u32 bh[2][4], bl[2][4];
#pragma unroll
            for (int bt = 0; bt < 2; ++bt) {
                const u32 rb = (wn * 32 + bt * 16 + lrow) * ROWB + coff;
                ldsm4(bh[bt], sb + BBUF_HI + rb);
                ldsm4(bl[bt], sb + BBUF_LO + rb);
            }
#pragma unroll
            for (int mt = 0; mt < 4; ++mt)
#pragma unroll
                for (int nt = 0; nt < 4; ++nt) {
                    const int bt = nt >> 1, hf = nt & 1;
                    mma16816(acc[mt][nt], ah[mt], bh[bt][hf], bh[bt][hf + 2]);
                    mma16816(acc[mt][nt], ah[mt], bl[bt][hf], bl[bt][hf + 2]);
                    mma16816(acc[mt][nt], al[mt], bh[bt][hf], bh[bt][hf + 2]);
                }
        }
        __syncthreads();
    }

#pragma unroll
    for (int nt = 0; nt < 4; ++nt) {
        const int col = nBase + wn * 32 + nt * 8 + 2 * (l & 3);
        const float2 b2 = *(const float2*)(bias + col);
#pragma unroll
        for (int mt = 0; mt < 4; ++mt) {
            const int row = mBase + wm * 64 + mt * 16 + (l >> 2);
            float2 r0, r1;
            r0.x = act_apply(acc[mt][nt][0] + b2.x, act);
            r0.y = act_apply(acc[mt][nt][1] + b2.y, act);
            r1.x = act_apply(acc[mt][nt][2] + b2.x, act);
            r1.y = act_apply(acc[mt][nt][3] + b2.y, act);
            *(float2*)(out + (size_t)row * D_ + col) = r0;
            *(float2*)(out + (size_t)(row + 8) * D_ + col) = r1;
        }
    }
}

// -------------------- tensor-core chunked scan --------------------
// Grid (16,8): batch b, 32-col j-slice. 512 thr, 16 warps; warp w owns
// i in [32w, 32w+32) with state as mma accum frags SA[2 mt][4 nt][4].
#define ST_I 1040
#define OQH 0
#define OQL (OQH + 16*ST_I)
#define OKH (OQL + 16*ST_I)
#define OKL (OKH + 16*ST_I)
#define OVH (OKL + 16*ST_I)
#define OVL (OVH + 32*48)
#define OPH (OVL + 32*48)
#define OPL (OPH + 16*48)
#define OAC (OPL + 16*48)
#define OPP (OAC + 2048)
#define OPA (OPP + 256*17*4)
#define ONA (OPA + 16*528*4)
#define ODN (ONA + 528*4)
#define ODP (ODN + 512*17*4)
#define SCAN_SMEM (ODP + 528*4)

__global__ void __launch_bounds__(512, 1) scan_mma_kernel(float* __restrict__ y)
{
    extern __shared__ __align__(16) char sm[];
    const u32 sb = smem_u32(sm);
    float* fAC = (float*)(sm + OAC);
    float* fPP = (float*)(sm + OPP);
    float* fPA = (float*)(sm + OPA);
    float* fNA = (float*)(sm + ONA);
    float* fDN = (float*)(sm + ODN);
    float* fDP = (float*)(sm + ODP);

    const int b = blockIdx.y, jbase = blockIdx.x * 32;
    const int tid = threadIdx.x, w = tid >> 5, l = tid & 31;
    const float* gq = g_q + (size_t)b * S_ * D_;
    const float* gk = g_k + (size_t)b * S_ * D_;
    const float* gv = g_v + (size_t)b * S_ * D_;
    const float* ga = g_a + (size_t)b * S_ * D_;
    float* gy = y + (size_t)b * S_ * D_;

    float SA[2][4][4];
#pragma unroll
    for (int mt = 0; mt < 2; ++mt)
#pragma unroll
        for (int nt = 0; nt < 4; ++nt)
#pragma unroll
            for (int e = 0; e < 4; ++e) SA[mt][nt][e] = 0.0f;
    float zreg = 0.0f;

    const int l7 = l & 7;
    // plain A/B frag addressing on [t][i] (stride ST_I): rows (l7 | +8 by bit3), col half by bit4
    const u32 aTI  = (u32)((l7 + 8 * ((l >> 3) & 1)) * ST_I + 16 * (l >> 4));
    // trans A frag on [t][i]: rows by bit4, col half by bit3
    const u32 aTIt = (u32)((l7 + 8 * ((l >> 4) & 1)) * ST_I + 16 * ((l >> 3) & 1));
    // plain frag on stride-48 arrays ([j][t] and [t][t'])
    const u32 a48  = (u32)((l7 + 8 * ((l >> 3) & 1)) * 48 + 16 * (l >> 4));

#pragma unroll 1
    for (int ch = 0; ch < NCH_; ++ch) {
        const int t0 = ch * C_;
        __syncthreads();   // B0

        // ---- stage: decay prep, z/den, bf16 staging into [t][i] ----
        {
            const int i_ = tid;
            float av[16], A[16], iA[16], qv[16], kv[16];
#pragma unroll
            for (int t = 0; t < 16; ++t) av[t] = ga[(size_t)(t0 + t) * D_ + i_];
#pragma unroll
            for (int t = 0; t < 16; ++t) qv[t] = gq[(size_t)(t0 + t) * D_ + i_];
#pragma unroll
            for (int t = 0; t < 16; ++t) kv[t] = gk[(size_t)(t0 + t) * D_ + i_];
            A[0] = av[0];
#pragma unroll
            for (int t = 1; t < 16; ++t) A[t] = A[t - 1] * av[t];
            iA[15] = __frcp_rn(A[15]);
#pragma unroll
            for (int t = 15; t >= 1; --t) iA[t - 1] = iA[t] * av[t];
            float zu = zreg;
#pragma unroll
            for (int t = 0; t < 16; ++t) {
                const float qt = qv[t] * A[t];
                const float kt = kv[t] * iA[t];
                zu += kt;
                fDN[i_ * 17 + t] = qt * zu;
                const __nv_bfloat16 qh = __float2bfloat16(qt);
                const __nv_bfloat16 kh = __float2bfloat16(kt);
                *(__nv_bfloat16*)(sm + OQH + t * ST_I + i_ * 2) = qh;
                *(__nv_bfloat16*)(sm + OQL + t * ST_I + i_ * 2) =
                    __float2bfloat16(qt - __bfloat162float(qh));
                *(__nv_bfloat16*)(sm + OKH + t * ST_I + i_ * 2) = kh;
                *(__nv_bfloat16*)(sm + OKL + t * ST_I + i_ * 2) =
                    __float2bfloat16(kt - __bfloat162float(kh));
            }
            zreg = A[15] * zu;
            fAC[i_] = A[15];
        }
        // V staging [j][t]
        {
            const int t = tid >> 5, j = l;
            const float vv = gv[(size_t)(t0 + t) * D_ + jbase + j];
            const __nv_bfloat16 vh = __float2bfloat16(vv);
            *(__nv_bfloat16*)(sm + OVH + j * 48 + t * 2) = vh;
            *(__nv_bfloat16*)(sm + OVL + j * 48 + t * 2) =
                __float2bfloat16(vv - __bfloat162float(vh));
        }
        __syncthreads();   // B1

        // ---- mma phase ----
        u32 qhf[2][4], qlf[2][4];
        {
            // P = Q~ K~^T partial over warp's i-32
            u32 khf[2][4], klf[2][4];
#pragma unroll
            for (int ks = 0; ks < 2; ++ks) {
                const u32 io = (u32)(w * 32 + ks * 16) * 2;
                ldsm4(qhf[ks], sb + OQH + aTI + io);
                ldsm4(qlf[ks], sb + OQL + aTI + io);
                ldsm4(khf[ks], sb + OKH + aTI + io);
                ldsm4(klf[ks], sb + OKL + aTI + io);
            }
            float p0[4] = {0, 0, 0, 0}, p1[4] = {0, 0, 0, 0};
#pragma unroll
            for (int ks = 0; ks < 2; ++ks) {
                mma16816(p0, qhf[ks], khf[ks][0], khf[ks][2]);
                mma16816(p0, qlf[ks], khf[ks][0], khf[ks][2]);
                mma16816(p0, qhf[ks], klf[ks][0], klf[ks][2]);
                mma16816(p1, qhf[ks], khf[ks][1], khf[ks][3]);
                mma16816(p1, qlf[ks], khf[ks][1], khf[ks][3]);
                mma16816(p1, qhf[ks], klf[ks][1], klf[ks][3]);
            }
#pragma unroll
            for (int e = 0; e < 4; ++e) {
                const int tr = (l >> 2) + (e >> 1) * 8;
                const int tc = 2 * (l & 3) + (e & 1);
                fPP[(tr * 16 + tc) * 17 + w] = p0[e];
                fPP[(tr * 16 + tc + 8) * 17 + w] = p1[e];
            }
        }
        {
            // NumA = Q~ S0 partial (state as B via movmatrix)
            float qs[4][4];
#pragma unroll
            for (int nt = 0; nt < 4; ++nt)
#pragma unroll
                for (int e = 0; e < 4; ++e) qs[nt][e] = 0.0f;
#pragma unroll
            for (int mt = 0; mt < 2; ++mt)
#pragma unroll
                for (int nt = 0; nt < 4; ++nt) {
                    const float c0 = SA[mt][nt][0], c1 = SA[mt][nt][1];
                    const float c2 = SA[mt][nt][2], c3 = SA[mt][nt][3];
                    const u32 b0h = movmt(bfpack(c0, c1));
                    const u32 b1h = movmt(bfpack(c2, c3));
                    const u32 b0l = movmt(bfpack(bfres(c0), bfres(c1)));
                    const u32 b1l = movmt(bfpack(bfres(c2), bfres(c3)));
                    mma16816(qs[nt], qhf[mt], b0h, b1h);
                    mma16816(qs[nt], qlf[mt], b0h, b1h);
                    mma16816(qs[nt], qhf[mt], b0l, b1l);
                }
#pragma unroll
            for (int nt = 0; nt < 4; ++nt)
#pragma unroll
                for (int e = 0; e < 4; ++e) {
                    const int tr = (l >> 2) + (e >> 1) * 8;
                    const int j = nt * 8 + 2 * (l & 3) + (e & 1);
                    fPA[w * 528 + tr * 33 + j] = qs[nt][e];
                }
        }
        {
            // State update S += K~^T V, then scale by A_C
            u32 ah[2][4], al[2][4], vh[2][4], vl[2][4];
#pragma unroll
            for (int mt = 0; mt < 2; ++mt) {
                const u32 io = (u32)(w * 32 + mt * 16) * 2;
                ldsm4t(ah[mt], sb + OKH + aTIt + io);
                ldsm4t(al[mt], sb + OKL + aTIt + io);
            }
#pragma unroll
            for (int jg = 0; jg < 2; ++jg) {
                ldsm4(vh[jg], sb + OVH + a48 + jg * 768);
                ldsm4(vl[jg], sb + OVL + a48 + jg * 768);
            }
#pragma unroll
            for (int mt = 0; mt < 2; ++mt)
#pragma unroll
                for (int nt = 0; nt < 4; ++nt) {
                    const int jg = nt >> 1, hf = nt & 1;
                    mma16816(SA[mt][nt], ah[mt], vh[jg][hf], vh[jg][hf + 2]);
                    mma16816(SA[mt][nt], al[mt], vh[jg][hf], vh[jg][hf + 2]);
                    mma16816(SA[mt][nt], ah[mt], vl[jg][hf], vl[jg][hf + 2]);
                }
#pragma unroll
            for (int mt = 0; mt < 2; ++mt) {
                const float s0 = fAC[w * 32 + mt * 16 + (l >> 2)];
                const float s8 = fAC[w * 32 + mt * 16 + 8 + (l >> 2)];
#pragma unroll
                for (int nt = 0; nt < 4; ++nt) {
                    SA[mt][nt][0] *= s0; SA[mt][nt][1] *= s0;
                    SA[mt][nt][2] *= s8; SA[mt][nt][3] *= s8;
                }
            }
        }
        __syncthreads();   // B2

        // ---- reduce phase ----
        {
            const int t = tid >> 5, j = l;
            float s = 0.0f;
#pragma unroll
            for (int ww = 0; ww < 16; ++ww) s += fPA[ww * 528 + t * 33 + j];
            fNA[t * 33 + j] = s;
        }
        if (tid < 256) {
            const int t = tid >> 4, tp = tid & 15;
            float p = 0.0f;
            if (tp <= t) {
#pragma unroll
                for (int ww = 0; ww < 16; ++ww) p += fPP[(t * 16 + tp) * 17 + ww];
            }
            const __nv_bfloat16 ph = __float2bfloat16(p);
            *(__nv_bfloat16*)(sm + OPH + t * 48 + tp * 2) = ph;
            *(__nv_bfloat16*)(sm + OPL + t * 48 + tp * 2) =
                __float2bfloat16(p - __bfloat162float(ph));
        }
        {
            const int t = tid & 15, g = tid >> 4;
            float s = 0.0f;
#pragma unroll
            for (int m = 0; m < 16; ++m) s += fDN[(g * 16 + m) * 17 + t];
            fDP[t * 33 + g] = s;
        }
        __syncthreads();   // B3

        // ---- output: warps 0-1 compute P.V, add NumA, divide, store ----
        if (w < 2) {
            const int tt = l & 15, hh = l >> 4;
            float dn = 0.0f;
#pragma unroll
            for (int g2 = 0; g2 < 16; ++g2) dn += fDP[tt * 33 + hh * 16 + g2];
            dn += __shfl_xor_sync(0xffffffffu, dn, 16);
            const float inv = 1.0f / (dn + kEPS);
            const float i0v = __shfl_sync(0xffffffffu, inv, l >> 2);
            const float i8v = __shfl_sync(0xffffffffu, inv, (l >> 2) + 8);

            u32 pa[4], pb[4], vvh[4], vvl[4];
            ldsm4(pa, sb + OPH + a48);
            ldsm4(pb, sb + OPL + a48);
            ldsm4(vvh, sb + OVH + a48 + w * 768);
            ldsm4(vvl, sb + OVL + a48 + w * 768);
            float o0[4] = {0, 0, 0, 0}, o1[4] = {0, 0, 0, 0};
            mma16816(o0, pa, vvh[0], vvh[2]);
            mma16816(o0, pb, vvh[0], vvh[2]);
            mma16816(o0, pa, vvl[0], vvl[2]);
            mma16816(o1, pa, vvh[1], vvh[3]);
            mma16816(o1, pb, vvh[1], vvh[3]);
            mma16816(o1, pa, vvl[1], vvl[3]);

#pragma unroll
            for (int h2 = 0; h2 < 2; ++h2) {
                const float* oo = h2 ? o1 : o0;
                const int cb = w * 16 + h2 * 8 + 2 * (l & 3);
#pragma unroll
                for (int e = 0; e < 4; ++e) {
                    const int tr = (l >> 2) + (e >> 1) * 8;
                    const int cc = cb + (e & 1);
                    const float val = (fNA[tr * 33 + cc] + oo[e]) *
                                      ((e >> 1) ? i8v : i0v);
                    gy[(size_t)(t0 + tr) * D_ + jbase + cc] = val;
                }
            }
        }
    }
}

// -------------------- launch --------------------
extern "C" void kernel_launch(void* const* d_in, const int* in_sizes, int n_in,
                              void* d_out, int out_size)
{
    const float* x  = (const float*)d_in[0];
    const float* Wq = (const float*)d_in[1];
    const float* bq = (const float*)d_in[2];
    const float* Wk = (const float*)d_in[3];
    const float* bk = (const float*)d_in[4];
    const float* Wv = (const float*)d_in[5];
    const float* bv = (const float*)d_in[6];
    const float* Wa = (const float*)d_in[7];
    const float* ba = (const float*)d_in[8];
    float* y = (float*)d_out;

    static __nv_bfloat16 *p_xhi = nullptr, *p_xlo = nullptr;
    if (!p_xhi) {
        cudaGetSymbolAddress((void**)&p_xhi, g_xhi);
        cudaGetSymbolAddress((void**)&p_xlo, g_xlo);
    }

    convert_split_kernel<<<2048, 256>>>(x, p_xhi, p_xlo, (M_TOT * D_) / 2);
    dim3 wgrid(64, 4);
    convert_w_kernel<<<wgrid, 256>>>(Wq, Wk, Wv, Wa);

    cudaFuncSetAttribute(proj_mma_kernel,
                         cudaFuncAttributeMaxDynamicSharedMemorySize, GEMM_SMEM);
    dim3 ggrid(D_ / 128, M_TOT / 128, 4);
    proj_mma_kernel<<<ggrid, 256, GEMM_SMEM>>>(bq, bk, bv, ba);

    cudaFuncSetAttribute(scan_mma_kernel,
                         cudaFuncAttributeMaxDynamicSharedMemorySize, SCAN_SMEM);
    dim3 sgrid(D_ / 32, B_);
    scan_mma_kernel<<<sgrid, 512, SCAN_SMEM>>>(y);
}